// round 12
// baseline (speedup 1.0000x reference)
#include <cuda_runtime.h>
#include <cuda_bf16.h>
#include <math.h>
#include <stdint.h>

#define BB 4
#define LL 8192
#define DM 64
#define HH 8
#define DFF 256
#define UU 50
#define ROWS (BB*LL)
#define CHUNK 512
#define NSPLIT 16
#define VSEG 64

typedef unsigned long long u64;

__device__ __align__(16) float g_x[ROWS*DM];
__device__ __align__(16) float g_q[ROWS*DM];
__device__ __align__(16) float g_k[ROWS*DM];
__device__ __align__(16) float g_v[ROWS*DM];
__device__ __align__(16) __nv_bfloat16 g_kh[ROWS*DM];
__device__ __align__(16) float g_ctx[ROWS*DM];
__device__ __align__(16) float g_pe[LL*DM];
__device__ float g_M[BB*HH*LL];
__device__ int   g_top[BB*HH*UU];
__device__ float g_vpart[BB*VSEG*DM];
__device__ float g_vmean[BB*DM];
__device__ float g_part[BB*HH*UU*NSPLIT*10];
__device__ float2 g_div[32];
// packed (w,w) weights
__device__ __align__(16) u64 g_wqp[2*DM*DM];
__device__ __align__(16) u64 g_wkp[2*DM*DM];
__device__ __align__(16) u64 g_wvp[2*DM*DM];
__device__ __align__(16) u64 g_wop[2*DM*DM];
__device__ __align__(16) u64 g_w1p[2*DM*DFF];
__device__ __align__(16) u64 g_w2p[2*DFF*DM];

// ---- packed fp32x2 helpers (bit-exact: each half is an IEEE fp32 FMA) ----
__device__ __forceinline__ u64 pk2(float lo, float hi) {
    u64 r;
    asm("mov.b64 %0, {%1, %2};" : "=l"(r) : "r"(__float_as_uint(lo)), "r"(__float_as_uint(hi)));
    return r;
}
__device__ __forceinline__ void upk2(u64 v, float &lo, float &hi) {
    unsigned a, b;
    asm("mov.b64 {%0, %1}, %2;" : "=r"(a), "=r"(b) : "l"(v));
    lo = __uint_as_float(a); hi = __uint_as_float(b);
}
__device__ __forceinline__ void fma2(u64 &d, u64 a, u64 b) {
    asm("fma.rn.f32x2 %0, %1, %2, %0;" : "+l"(d) : "l"(a), "l"(b));
}

__device__ __forceinline__ unsigned fkey(float f) {
    unsigned u = __float_as_uint(f);
    return (u & 0x80000000u) ? ~u : (u | 0x80000000u);
}

__global__ void k_pack(const float* __restrict__ src, u64* __restrict__ dst, int n) {
    int i = blockIdx.x*256 + threadIdx.x;
    if (i < n) { float v = src[i]; dst[i] = pk2(v, v); }
}

__global__ void k_div() {
    int i = threadIdx.x;
    double dvd = exp(((double)(-2*i)) * (log(10000.0) / 64.0));
    float hi = (float)dvd;
    g_div[i] = make_float2(hi, (float)(dvd - (double)hi));
}

// PE computed once per (l,d) — shared by all batches
__global__ void k_pe() {
    int gid = blockIdx.x*256 + threadIdx.x;   // LL*DM
    int d = gid & 63, l = gid >> 6;
    float2 dv = g_div[d >> 1];
    float lf = (float)l;
    float ph = lf * dv.x;
    float perr = fmaf(lf, dv.x, -ph);
    float plo = fmaf(lf, dv.y, perr);
    float kq = rintf(ph * 0.63661977236758134f);
    float r = fmaf(-kq, 1.57079637050628662109375f, ph);
    r = fmaf(kq, 4.37113900018624283e-08f, r);
    r += plo;
    int qd = (((int)kq) + (d & 1)) & 3;
    float sr = sinf(r), cr = cosf(r);
    g_pe[gid] = (qd == 0) ? sr : (qd == 1) ? cr : (qd == 2) ? -sr : -cr;
}

__global__ void k_embed(const float* __restrict__ xe, const float* __restrict__ ew) {
    int gid = blockIdx.x*256 + threadIdx.x;
    int d = gid & 63, row = gid >> 6;
    int l = row & (LL-1), b = row >> 13;
    const float* xb = xe + b*LL;
    float tok = ew[d*3+0]*xb[(l+LL-1)&(LL-1)] + ew[d*3+1]*xb[l] + ew[d*3+2]*xb[(l+1)&(LL-1)];
    g_x[gid] = tok + g_pe[gid & (LL*DM - 1)];
}

__global__ __launch_bounds__(256) void k_qkv(
    const u64* __restrict__ Wq, const float* __restrict__ bq,
    const u64* __restrict__ Wk, const float* __restrict__ bk,
    const u64* __restrict__ Wv, const float* __restrict__ bv)
{
    __shared__ __align__(16) float xT[64*36];
    int row0 = blockIdx.x * 32, tid = threadIdx.x;
    for (int i = tid; i < 2048; i += 256) { int c=i&63, r=i>>6; xT[c*36+r] = g_x[(row0+r)*64+c]; }
    __syncthreads();
    int col = tid & 63, rg = tid >> 6;
    u64 aq2[4], ak2[4], av2[4];
    #pragma unroll
    for (int p = 0; p < 4; p++) { aq2[p]=0ull; ak2[p]=0ull; av2[p]=0ull; }
    #pragma unroll 4
    for (int kk = 0; kk < 64; kk++) {
        u64 wq2 = Wq[kk*64+col];
        u64 wk2 = Wk[kk*64+col];
        u64 wv2 = Wv[kk*64+col];
        const u64* xp = reinterpret_cast<const u64*>(&xT[kk*36 + rg*8]);
        #pragma unroll
        for (int p = 0; p < 4; p++) {
            u64 xv = xp[p];
            fma2(aq2[p], xv, wq2);
            fma2(ak2[p], xv, wk2);
            fma2(av2[p], xv, wv2);
        }
    }
    float b1 = bq[col], b2 = bk[col], b3 = bv[col];
    #pragma unroll
    for (int p = 0; p < 4; p++) {
        float q0,q1,k0,k1,v0,v1;
        upk2(aq2[p], q0, q1); upk2(ak2[p], k0, k1); upk2(av2[p], v0, v1);
        int row = row0 + rg*8 + 2*p;
        float kv0 = k0 + b2, kv1 = k1 + b2;
        g_q[row*64+col] = q0 + b1;       g_q[(row+1)*64+col] = q1 + b1;
        g_k[row*64+col] = kv0;           g_k[(row+1)*64+col] = kv1;
        g_kh[row*64+col] = __float2bfloat16(kv0);
        g_kh[(row+1)*64+col] = __float2bfloat16(kv1);
        g_v[row*64+col] = v0 + b3;       g_v[(row+1)*64+col] = v1 + b3;
    }
}

// M-score via bf16 shadow-k: 32 lanes = 4 rows x 8 heads; 16B load = one head row-slice
__global__ __launch_bounds__(256) void k_mscore(const int* __restrict__ idxs)
{
    int wid = blockIdx.x*8 + (threadIdx.x>>5);
    int lane = threadIdx.x & 31;
    int b = wid >> 13, l = wid & (LL-1);
    const int* ib = idxs + l*UU;
    int i1 = ib[lane];
    int i2 = (lane < 18) ? ib[32+lane] : 0;
    int h = lane & 7;
    int rgrp = lane >> 3;
    const float4* qp = reinterpret_cast<const float4*>(g_q + (b*LL + l)*64 + h*8);
    float4 qa = qp[0], qb_ = qp[1];
    float runmax = -INFINITY, runsum = 0.f;
    #pragma unroll
    for (int it = 0; it < 13; it++) {
        int r = it*4 + rgrp;
        int idx = (r < 32) ? __shfl_sync(0xffffffffu, i1, r)
                           : __shfl_sync(0xffffffffu, i2, r-32);
        if (r < UU) {
            uint4 raw = reinterpret_cast<const uint4*>(g_kh + (b*LL + idx)*64)[h];
            float2 f0 = __bfloat1622float2(*reinterpret_cast<__nv_bfloat162*>(&raw.x));
            float2 f1 = __bfloat1622float2(*reinterpret_cast<__nv_bfloat162*>(&raw.y));
            float2 f2 = __bfloat1622float2(*reinterpret_cast<__nv_bfloat162*>(&raw.z));
            float2 f3 = __bfloat1622float2(*reinterpret_cast<__nv_bfloat162*>(&raw.w));
            float dd = qa.x*f0.x;
            dd = fmaf(qa.y, f0.y, dd);
            dd = fmaf(qa.z, f1.x, dd);
            dd = fmaf(qa.w, f1.y, dd);
            dd = fmaf(qb_.x, f2.x, dd);
            dd = fmaf(qb_.y, f2.y, dd);
            dd = fmaf(qb_.z, f3.x, dd);
            dd = fmaf(qb_.w, f3.y, dd);
            runmax = fmaxf(runmax, dd);
            runsum += dd;
        }
    }
    runmax = fmaxf(runmax, __shfl_xor_sync(0xffffffffu, runmax, 8));
    runsum +=              __shfl_xor_sync(0xffffffffu, runsum, 8);
    runmax = fmaxf(runmax, __shfl_xor_sync(0xffffffffu, runmax, 16));
    runsum +=              __shfl_xor_sync(0xffffffffu, runsum, 16);
    if (lane < 8)
        g_M[(b*HH + h)*LL + l] = runmax - runsum * (1.0f/8192.0f);
}

// Exact top-50 as a SET via 4-pass MSB radix select
__global__ __launch_bounds__(256) void k_topk()
{
    __shared__ unsigned sK[8192];
    __shared__ int hist[256];
    __shared__ unsigned sPrefix;
    __shared__ int sRem;
    __shared__ int cnt, eqcnt;
    __shared__ int eqbuf[256];
    int bh = blockIdx.x, tid = threadIdx.x;
    const float* base = g_M + bh*LL;
    for (int i = tid; i < 8192; i += 256) sK[i] = fkey(base[i]);
    if (tid == 0) { sPrefix = 0; sRem = UU; cnt = 0; eqcnt = 0; }
    __syncthreads();
    unsigned prefmask = 0;
    #pragma unroll
    for (int pass = 0; pass < 4; pass++) {
        int shift = 24 - 8*pass;
        hist[tid] = 0;
        __syncthreads();
        unsigned pref = sPrefix;
        for (int i = tid; i < 8192; i += 256) {
            unsigned u = sK[i];
            if ((u & prefmask) == pref)
                atomicAdd(&hist[(u >> shift) & 0xffu], 1);
        }
        __syncthreads();
        if (tid == 0) {
            int acc = 0, rem = sRem;
            for (int bkt = 255; bkt >= 0; bkt--) {
                int hh = hist[bkt];
                if (acc + hh >= rem) { sPrefix = pref | ((unsigned)bkt << shift); sRem = rem - acc; break; }
                acc += hh;
            }
        }
        __syncthreads();
        prefmask |= 0xffu << shift;
    }
    unsigned T = sPrefix;
    int need = sRem;
    for (int i = tid; i < 8192; i += 256) {
        unsigned u = sK[i];
        if (u > T) {
            int p = atomicAdd(&cnt, 1);
            g_top[bh*UU + p] = i;
        } else if (u == T) {
            int p = atomicAdd(&eqcnt, 1);
            if (p < 256) eqbuf[p] = i;
        }
    }
    __syncthreads();
    if (tid == 0) {
        int basep = cnt;
        int ec = eqcnt < 256 ? eqcnt : 256;
        for (int r = 0; r < need; r++) {
            int best = 0x7fffffff, bj = 0;
            for (int j = 0; j < ec; j++)
                if (eqbuf[j] < best) { best = eqbuf[j]; bj = j; }
            eqbuf[bj] = 0x7fffffff;
            g_top[bh*UU + basep + r] = best;
        }
    }
}

__global__ void k_vpart()
{
    __shared__ float sm[4][64];
    int b = blockIdx.x >> 6, seg = blockIdx.x & 63;
    int d = threadIdx.x & 63, lg = threadIdx.x >> 6;
    const float* base = g_v + (b*LL + seg*128 + lg*32)*64 + d;
    float s = 0.f;
    #pragma unroll 8
    for (int i = 0; i < 32; i++) s += base[i*64];
    sm[lg][d] = s;
    __syncthreads();
    if (threadIdx.x < 64)
        g_vpart[(b*VSEG + seg)*64 + threadIdx.x] =
            sm[0][threadIdx.x] + sm[1][threadIdx.x] + sm[2][threadIdx.x] + sm[3][threadIdx.x];
}

__global__ void k_vmean()
{
    int t = threadIdx.x;
    int b = t >> 6, d = t & 63;
    float s = 0.f;
    #pragma unroll
    for (int i = 0; i < VSEG; i++) s += g_vpart[(b*VSEG+i)*64 + d];
    g_vmean[t] = s * (1.0f/8192.0f);
}

__global__ void k_vmc()
{
    int gid = blockIdx.x*256 + threadIdx.x;
    g_ctx[gid] = g_vmean[((gid >> 19) << 6) | (gid & 63)];
}

template<int G>
__device__ __forceinline__ void attn_group(
    int u0, int bh, int b, int h, int lane, int split,
    const float* kT, const float* vT)
{
    const float SCALE = 0.35355339059327373f;
    float4 qa[G], qb[G];
    int uu[G]; bool val[G];
    #pragma unroll
    for (int g = 0; g < G; g++) {
        int u = u0 + g*8;
        val[g] = (u < UU);
        uu[g] = val[g] ? u : 0;
        int qi = g_top[bh*UU + uu[g]];
        const float4* qp = reinterpret_cast<const float4*>(g_q + (b*LL + qi)*64 + h*8);
        qa[g] = qp[0]; qb[g] = qp[1];
    }
    float ssum[G];
    u64 pv2[G][4];
    #pragma unroll
    for (int g = 0; g < G; g++) {
        ssum[g] = 0.f;
        #pragma unroll
        for (int e = 0; e < 4; e++) pv2[g][e] = 0ull;
    }
    for (int j = lane; j < CHUNK; j += 32) {
        float k0 = kT[j],        k1 = kT[520+j],   k2 = kT[2*520+j], k3 = kT[3*520+j];
        float k4 = kT[4*520+j],  k5 = kT[5*520+j], k6 = kT[6*520+j], k7 = kT[7*520+j];
        u64 v01 = pk2(vT[j],        vT[520+j]);
        u64 v23 = pk2(vT[2*520+j],  vT[3*520+j]);
        u64 v45 = pk2(vT[4*520+j],  vT[5*520+j]);
        u64 v67 = pk2(vT[6*520+j],  vT[7*520+j]);
        #pragma unroll
        for (int g = 0; g < G; g++) {
            float s = qa[g].x*k0;
            s = fmaf(qa[g].y, k1, s);
            s = fmaf(qa[g].z, k2, s);
            s = fmaf(qa[g].w, k3, s);
            s = fmaf(qb[g].x, k4, s);
            s = fmaf(qb[g].y, k5, s);
            s = fmaf(qb[g].z, k6, s);
            s = fmaf(qb[g].w, k7, s);
            float p = __expf(s * SCALE);
            ssum[g] += p;
            u64 p2 = pk2(p, p);
            fma2(pv2[g][0], v01, p2);
            fma2(pv2[g][1], v23, p2);
            fma2(pv2[g][2], v45, p2);
            fma2(pv2[g][3], v67, p2);
        }
    }
    #pragma unroll
    for (int g = 0; g < G; g++) {
        float pv[8];
        #pragma unroll
        for (int e = 0; e < 4; e++) upk2(pv2[g][e], pv[2*e], pv[2*e+1]);
        #pragma unroll
        for (int o = 16; o; o >>= 1) {
            ssum[g] += __shfl_xor_sync(0xffffffffu, ssum[g], o);
            #pragma unroll
            for (int e = 0; e < 8; e++) pv[e] += __shfl_xor_sync(0xffffffffu, pv[e], o);
        }
        if (lane == 0 && val[g]) {
            float* pp = g_part + ((bh*UU + uu[g])*NSPLIT + split)*10;
            #pragma unroll
            for (int e = 0; e < 8; e++) pp[e] = pv[e];
            pp[8] = ssum[g];
        }
    }
}

__global__ __launch_bounds__(256) void k_attn()
{
    __shared__ float kT[8*520];
    __shared__ float vT[8*520];
    int bh = blockIdx.x >> 4, split = blockIdx.x & 15;
    int b = bh >> 3, h = bh & 7;
    int l0 = split * CHUNK, tid = threadIdx.x;
    for (int i = tid; i < CHUNK*8; i += 256) {
        int j = i >> 3, e = i & 7;
        int g = (b*LL + l0 + j)*64 + h*8 + e;
        kT[e*520 + j] = g_k[g];
        vT[e*520 + j] = g_v[g];
    }
    __syncthreads();
    int w = tid >> 5, lane = tid & 31;
    attn_group<4>(w,      bh, b, h, lane, split, kT, vT);
    attn_group<3>(w + 32, bh, b, h, lane, split, kT, vT);
}

__global__ void k_merge()
{
    int gid = blockIdx.x*256 + threadIdx.x;
    int e = gid & 7, rest = gid >> 3;
    int u = rest % UU, bh = rest / UU;
    int b = bh >> 3, h = bh & 7;
    const float* pp = g_part + ((bh*UU + u)*NSPLIT)*10;
    float pv = 0.f, ss = 0.f;
    for (int s = 0; s < NSPLIT; s++) { pv += pp[s*10 + e]; ss += pp[s*10 + 8]; }
    int qi = g_top[bh*UU + u];
    g_ctx[(b*LL + qi)*64 + h*8 + e] = pv / ss;
}

__device__ __forceinline__ void ln_epilogue(float* out65, int row0, int tid,
    const float* __restrict__ lg, const float* __restrict__ lb)
{
    int w = tid >> 5, lane = tid & 31;
    float gg0 = lg[lane], gg1 = lg[lane+32], bb0 = lb[lane], bb1 = lb[lane+32];
    #pragma unroll
    for (int rr = 0; rr < 4; rr++) {
        int r = w*4 + rr;
        float v0 = out65[r*65 + lane], v1 = out65[r*65 + lane + 32];
        float s = v0 + v1;
        #pragma unroll
        for (int o = 16; o; o >>= 1) s += __shfl_xor_sync(0xffffffffu, s, o);
        float mean = s * (1.0f/64.0f);
        float d0 = v0 - mean, d1 = v1 - mean;
        float s2 = d0*d0 + d1*d1;
        #pragma unroll
        for (int o = 16; o; o >>= 1) s2 += __shfl_xor_sync(0xffffffffu, s2, o);
        float inv = rsqrtf(s2 * (1.0f/64.0f) + 1e-5f);
        int go = (row0 + r)*64;
        g_x[go + lane]      = fmaf(d0 * inv, gg0, bb0);
        g_x[go + lane + 32] = fmaf(d1 * inv, gg1, bb1);
    }
}

__global__ __launch_bounds__(256) void k_wo_ln(
    const u64* __restrict__ W, const float* __restrict__ bo,
    const float* __restrict__ lg, const float* __restrict__ lb)
{
    __shared__ __align__(16) float xT[64*36];
    __shared__ float out[32*65];
    int row0 = blockIdx.x * 32, tid = threadIdx.x;
    for (int i = tid; i < 2048; i += 256) { int c=i&63, r=i>>6; xT[c*36+r] = g_ctx[(row0+r)*64+c]; }
    __syncthreads();
    int col = tid & 63, rg = tid >> 6;
    u64 acc2[4];
    #pragma unroll
    for (int p = 0; p < 4; p++) acc2[p] = 0ull;
    #pragma unroll 4
    for (int kk = 0; kk < 64; kk++) {
        u64 w2 = W[kk*64+col];
        const u64* xp = reinterpret_cast<const u64*>(&xT[kk*36 + rg*8]);
        #pragma unroll
        for (int p = 0; p < 4; p++) fma2(acc2[p], xp[p], w2);
    }
    float bv2 = bo[col];
    #pragma unroll
    for (int p = 0; p < 4; p++) {
        float f0, f1;
        upk2(acc2[p], f0, f1);
        int r = rg*8 + 2*p;
        out[r*65 + col]     = f0 + bv2 + g_x[(row0 + r)*64 + col];
        out[(r+1)*65 + col] = f1 + bv2 + g_x[(row0 + r + 1)*64 + col];
    }
    __syncthreads();
    ln_epilogue(out, row0, tid, lg, lb);
}

__global__ __launch_bounds__(256) void k_ffn(
    const u64* __restrict__ W1, const float* __restrict__ b1,
    const u64* __restrict__ W2, const float* __restrict__ b2,
    const float* __restrict__ lg, const float* __restrict__ lb)
{
    __shared__ __align__(16) float yT[256*36];
    __shared__ __align__(16) float xTo[64*36];
    int row0 = blockIdx.x * 32, tid = threadIdx.x;
    for (int i = tid; i < 2048; i += 256) { int c=i&63, r=i>>6; xTo[c*36+r] = g_x[(row0+r)*64+c]; }
    __syncthreads();
    int col = tid & 63, rg = tid >> 6;
    u64 acc2[16];
    #pragma unroll
    for (int i = 0; i < 16; i++) acc2[i] = 0ull;
    #pragma unroll 2
    for (int kk = 0; kk < 64; kk++) {
        u64 w0 = W1[kk*256 + col];
        u64 w1 = W1[kk*256 + 64 + col];
        u64 w2 = W1[kk*256 + 128 + col];
        u64 w3 = W1[kk*256 + 192 + col];
        const u64* xp = reinterpret_cast<const u64*>(&xTo[kk*36 + rg*8]);
        #pragma unroll
        for (int p = 0; p < 4; p++) {
            u64 xv = xp[p];
            fma2(acc2[p],    xv, w0);
            fma2(acc2[4+p],  xv, w1);
            fma2(acc2[8+p],  xv, w2);
            fma2(acc2[12+p], xv, w3);
        }
    }
    __syncthreads();
    #pragma unroll
    for (int t = 0; t < 4; t++) {
        float bb = b1[t*64 + col];
        float f[8];
        #pragma unroll
        for (int p = 0; p < 4; p++) {
            float a, c;
            upk2(acc2[t*4+p], a, c);
            f[2*p]   = fmaxf(a + bb, 0.f);
            f[2*p+1] = fmaxf(c + bb, 0.f);
        }
        float4 f0 = {f[0], f[1], f[2], f[3]};
        float4 f1 = {f[4], f[5], f[6], f[7]};
        *reinterpret_cast<float4*>(&yT[(t*64+col)*36 + rg*8])     = f0;
        *reinterpret_cast<float4*>(&yT[(t*64+col)*36 + rg*8 + 4]) = f1;
    }
    __syncthreads();
    u64 a2[4];
    #pragma unroll
    for (int p = 0; p < 4; p++) a2[p] = 0ull;
    #pragma unroll 4
    for (int kk = 0; kk < 256; kk++) {
        u64 w2 = W2[kk*64 + col];
        const u64* yp = reinterpret_cast<const u64*>(&yT[kk*36 + rg*8]);
        #pragma unroll
        for (int p = 0; p < 4; p++) fma2(a2[p], yp[p], w2);
    }
    float bv2 = b2[col];
    float* out = xTo;
    #pragma unroll
    for (int p = 0; p < 4; p++) {
        float f0, f1;
        upk2(a2[p], f0, f1);
        int r = rg*8 + 2*p;
        out[r*65 + col]     = f0 + bv2 + g_x[(row0 + r)*64 + col];
        out[(r+1)*65 + col] = f1 + bv2 + g_x[(row0 + r + 1)*64 + col];
    }
    __syncthreads();
    ln_epilogue(out, row0, tid, lg, lb);
}

__global__ __launch_bounds__(256) void k_final(
    const float* __restrict__ lg, const float* __restrict__ lb,
    const float* __restrict__ pw, const float* __restrict__ pb,
    float* __restrict__ outp)
{
    int row = blockIdx.x*8 + (threadIdx.x >> 5);
    int lane = threadIdx.x & 31;
    const float* xr = g_x + row*64;
    float v0 = xr[lane], v1 = xr[lane+32];
    float s = v0 + v1;
    #pragma unroll
    for (int o = 16; o; o >>= 1) s += __shfl_xor_sync(0xffffffffu, s, o);
    float mean = s * (1.0f/64.0f);
    float d0 = v0 - mean, d1 = v1 - mean;
    float s2 = d0*d0 + d1*d1;
    #pragma unroll
    for (int o = 16; o; o >>= 1) s2 += __shfl_xor_sync(0xffffffffu, s2, o);
    float inv = rsqrtf(s2 * (1.0f/64.0f) + 1e-5f);
    float xn0 = fmaf(d0 * inv, lg[lane],    lb[lane]);
    float xn1 = fmaf(d1 * inv, lg[lane+32], lb[lane+32]);
    float lgt[5];
    #pragma unroll
    for (int c = 0; c < 5; c++) {
        float t = fmaf(xn0, pw[lane*5 + c], xn1 * pw[(lane+32)*5 + c]);
        #pragma unroll
        for (int o = 16; o; o >>= 1) t += __shfl_xor_sync(0xffffffffu, t, o);
        lgt[c] = t + pb[c];
    }
    float m = lgt[0];
    #pragma unroll
    for (int c = 1; c < 5; c++) m = fmaxf(m, lgt[c]);
    float e[5], se = 0.f;
    #pragma unroll
    for (int c = 0; c < 5; c++) { e[c] = __expf(lgt[c] - m); se += e[c]; }
    float rse = 1.0f / se;
    if (lane == 0) {
        #pragma unroll
        for (int c = 0; c < 5; c++) outp[row*5 + c] = e[c] * rse;
    }
}

extern "C" void kernel_launch(void* const* d_in, const int* in_sizes, int n_in,
                              void* d_out, int out_size)
{
    const float* x_enc   = (const float*)d_in[0];
    const int*   idxs    = (const int*)  d_in[1];
    const float* emb_w   = (const float*)d_in[2];
    const float* Wq      = (const float*)d_in[3];
    const float* bq      = (const float*)d_in[4];
    const float* Wk      = (const float*)d_in[5];
    const float* bk      = (const float*)d_in[6];
    const float* Wv      = (const float*)d_in[7];
    const float* bv      = (const float*)d_in[8];
    const float* Wo      = (const float*)d_in[9];
    const float* bo      = (const float*)d_in[10];
    const float* c1w     = (const float*)d_in[11];
    const float* c1b     = (const float*)d_in[12];
    const float* c2w     = (const float*)d_in[13];
    const float* c2b     = (const float*)d_in[14];
    const float* ln1g    = (const float*)d_in[15];
    const float* ln1b    = (const float*)d_in[16];
    const float* ln2g    = (const float*)d_in[17];
    const float* ln2b    = (const float*)d_in[18];
    const float* lnfg    = (const float*)d_in[19];
    const float* lnfb    = (const float*)d_in[20];
    const float* projw   = (const float*)d_in[21];
    const float* projb   = (const float*)d_in[22];
    float* outp = (float*)d_out;

    cudaStream_t s1;
    cudaStreamCreateWithFlags(&s1, cudaStreamNonBlocking);
    cudaEvent_t evS, evP, evF[2], evJ[2];
    cudaEventCreateWithFlags(&evS, cudaEventDisableTiming);
    cudaEventCreateWithFlags(&evP, cudaEventDisableTiming);
    for (int i = 0; i < 2; i++) {
        cudaEventCreateWithFlags(&evF[i], cudaEventDisableTiming);
        cudaEventCreateWithFlags(&evJ[i], cudaEventDisableTiming);
    }

    u64 *wqp, *wkp, *wvp, *wop, *w1p, *w2p;
    cudaGetSymbolAddress((void**)&wqp, g_wqp);
    cudaGetSymbolAddress((void**)&wkp, g_wkp);
    cudaGetSymbolAddress((void**)&wvp, g_wvp);
    cudaGetSymbolAddress((void**)&wop, g_wop);
    cudaGetSymbolAddress((void**)&w1p, g_w1p);
    cudaGetSymbolAddress((void**)&w2p, g_w2p);

    // CAPTURE-SAFE FORK: k_div is the first node on the capturing stream; s1 is
    // forked from it via event before any s1 launch (required under stream capture).
    k_div<<<1, 32>>>();
    cudaEventRecord(evS, 0);
    cudaStreamWaitEvent(s1, evS, 0);

    // weight packing on the (now-forked) side stream, overlapping pe/embed
    k_pack<<<(2*DM*DM+255)/256, 256, 0, s1>>>(Wq, wqp, 2*DM*DM);
    k_pack<<<(2*DM*DM+255)/256, 256, 0, s1>>>(Wk, wkp, 2*DM*DM);
    k_pack<<<(2*DM*DM+255)/256, 256, 0, s1>>>(Wv, wvp, 2*DM*DM);
    k_pack<<<(2*DM*DM+255)/256, 256, 0, s1>>>(Wo, wop, 2*DM*DM);
    k_pack<<<(2*DM*DFF+255)/256, 256, 0, s1>>>(c1w, w1p, 2*DM*DFF);
    k_pack<<<(2*DFF*DM+255)/256, 256, 0, s1>>>(c2w, w2p, 2*DFF*DM);
    cudaEventRecord(evP, s1);

    k_pe<<<LL*DM/256, 256>>>();
    k_embed<<<ROWS*DM/256, 256>>>(x_enc, emb_w);
    cudaStreamWaitEvent(0, evP, 0);   // packed weights ready before first GEMM

    for (int i = 0; i < 2; i++) {
        k_qkv<<<ROWS/32, 256>>>(wqp + i*DM*DM, bq + i*DM, wkp + i*DM*DM, bk + i*DM,
                                wvp + i*DM*DM, bv + i*DM);
        cudaEventRecord(evF[i], 0);
        cudaStreamWaitEvent(s1, evF[i], 0);
        k_vpart<<<BB*VSEG, 256, 0, s1>>>();
        k_vmean<<<1, BB*DM, 0, s1>>>();
        k_vmc<<<ROWS*DM/256, 256, 0, s1>>>();
        cudaEventRecord(evJ[i], s1);
        k_mscore<<<ROWS/8, 256>>>(idxs + i*LL*UU);
        k_topk<<<BB*HH, 256>>>();
        k_attn<<<BB*HH*NSPLIT, 256>>>();
        cudaStreamWaitEvent(0, evJ[i], 0);
        k_merge<<<BB*HH*UU*8/256, 256>>>();
        k_wo_ln<<<ROWS/32, 256>>>(wop + i*DM*DM, bo + i*DM, ln1g + i*DM, ln1b + i*DM);
        k_ffn<<<ROWS/32, 256>>>(w1p + i*DM*DFF, c1b + i*DFF, w2p + i*DFF*DM, c2b + i*DM,
                                ln2g + i*DM, ln2b + i*DM);
    }
    k_final<<<ROWS/8, 256>>>(lnfg, lnfb, projw, projb, outp);
}

// round 13
// speedup vs baseline: 1.0083x; 1.0083x over previous
#include <cuda_runtime.h>
#include <cuda_bf16.h>
#include <math.h>
#include <stdint.h>

#define BB 4
#define LL 8192
#define DM 64
#define HH 8
#define DFF 256
#define UU 50
#define ROWS (BB*LL)
#define CHUNK 512
#define NSPLIT 16
#define VSEG 64

typedef unsigned long long u64;

__device__ __align__(16) float g_x[ROWS*DM];
__device__ __align__(16) float g_q[ROWS*DM];
__device__ __align__(16) float g_k[ROWS*DM];
__device__ __align__(16) float g_v[ROWS*DM];
__device__ __align__(16) __nv_bfloat16 g_kh[ROWS*DM];
__device__ __align__(16) float g_ctx[ROWS*DM];
__device__ float g_M[BB*HH*LL];
__device__ int   g_top[BB*HH*UU];
__device__ float g_vpart[BB*VSEG*DM];
__device__ float g_vmean[BB*DM];
__device__ float g_part[BB*HH*UU*NSPLIT*10];
__device__ float2 g_div[32];
// packed (w,w) weights: [wq|wk|wv|wo|w1|w2] both layers
__device__ __align__(16) u64 g_wqp[2*DM*DM];
__device__ __align__(16) u64 g_wkp[2*DM*DM];
__device__ __align__(16) u64 g_wvp[2*DM*DM];
__device__ __align__(16) u64 g_wop[2*DM*DM];
__device__ __align__(16) u64 g_w1p[2*DM*DFF];
__device__ __align__(16) u64 g_w2p[2*DFF*DM];

// ---- packed fp32x2 helpers (bit-exact: each half is an IEEE fp32 FMA) ----
__device__ __forceinline__ u64 pk2(float lo, float hi) {
    u64 r;
    asm("mov.b64 %0, {%1, %2};" : "=l"(r) : "r"(__float_as_uint(lo)), "r"(__float_as_uint(hi)));
    return r;
}
__device__ __forceinline__ void upk2(u64 v, float &lo, float &hi) {
    unsigned a, b;
    asm("mov.b64 {%0, %1}, %2;" : "=r"(a), "=r"(b) : "l"(v));
    lo = __uint_as_float(a); hi = __uint_as_float(b);
}
__device__ __forceinline__ void fma2(u64 &d, u64 a, u64 b) {
    asm("fma.rn.f32x2 %0, %1, %2, %0;" : "+l"(d) : "l"(a), "l"(b));
}

__device__ __forceinline__ unsigned fkey(float f) {
    unsigned u = __float_as_uint(f);
    return (u & 0x80000000u) ? ~u : (u | 0x80000000u);
}

// single fused pack kernel: 98304 elements total
#define NQ (2*DM*DM)          // 8192
#define N1 (2*DM*DFF)         // 32768
__global__ void k_packall(
    const float* __restrict__ Wq, const float* __restrict__ Wk,
    const float* __restrict__ Wv, const float* __restrict__ Wo,
    const float* __restrict__ W1, const float* __restrict__ W2)
{
    int i = blockIdx.x*256 + threadIdx.x;   // 0 .. 98303
    const float* src; u64* dst; int off;
    if (i < NQ)              { src = Wq; dst = g_wqp; off = i; }
    else if (i < 2*NQ)       { src = Wk; dst = g_wkp; off = i - NQ; }
    else if (i < 3*NQ)       { src = Wv; dst = g_wvp; off = i - 2*NQ; }
    else if (i < 4*NQ)       { src = Wo; dst = g_wop; off = i - 3*NQ; }
    else if (i < 4*NQ + N1)  { src = W1; dst = g_w1p; off = i - 4*NQ; }
    else                     { src = W2; dst = g_w2p; off = i - 4*NQ - N1; }
    float v = src[off];
    dst[off] = pk2(v, v);
}

__global__ void k_div() {
    int i = threadIdx.x;
    double dvd = exp(((double)(-2*i)) * (log(10000.0) / 64.0));
    float hi = (float)dvd;
    g_div[i] = make_float2(hi, (float)(dvd - (double)hi));
}

__global__ void k_embed(const float* __restrict__ xe, const float* __restrict__ ew) {
    int gid = blockIdx.x*256 + threadIdx.x;
    int d = gid & 63, row = gid >> 6;
    int l = row & (LL-1), b = row >> 13;
    const float* xb = xe + b*LL;
    float tok = ew[d*3+0]*xb[(l+LL-1)&(LL-1)] + ew[d*3+1]*xb[l] + ew[d*3+2]*xb[(l+1)&(LL-1)];
    float2 dv = g_div[d >> 1];
    float lf = (float)l;
    float ph = lf * dv.x;
    float perr = fmaf(lf, dv.x, -ph);
    float plo = fmaf(lf, dv.y, perr);
    float kq = rintf(ph * 0.63661977236758134f);
    float r = fmaf(-kq, 1.57079637050628662109375f, ph);
    r = fmaf(kq, 4.37113900018624283e-08f, r);
    r += plo;
    int qd = (((int)kq) + (d & 1)) & 3;
    float sr = sinf(r), cr = cosf(r);
    float pe = (qd == 0) ? sr : (qd == 1) ? cr : (qd == 2) ? -sr : -cr;
    g_x[gid] = tok + pe;
}

__global__ __launch_bounds__(256) void k_qkv(
    const u64* __restrict__ Wq, const float* __restrict__ bq,
    const u64* __restrict__ Wk, const float* __restrict__ bk,
    const u64* __restrict__ Wv, const float* __restrict__ bv)
{
    __shared__ __align__(16) float xT[64*36];
    int row0 = blockIdx.x * 32, tid = threadIdx.x;
    for (int i = tid; i < 2048; i += 256) { int c=i&63, r=i>>6; xT[c*36+r] = g_x[(row0+r)*64+c]; }
    __syncthreads();
    int col = tid & 63, rg = tid >> 6;
    u64 aq2[4], ak2[4], av2[4];
    #pragma unroll
    for (int p = 0; p < 4; p++) { aq2[p]=0ull; ak2[p]=0ull; av2[p]=0ull; }
    #pragma unroll 4
    for (int kk = 0; kk < 64; kk++) {
        u64 wq2 = Wq[kk*64+col];
        u64 wk2 = Wk[kk*64+col];
        u64 wv2 = Wv[kk*64+col];
        const u64* xp = reinterpret_cast<const u64*>(&xT[kk*36 + rg*8]);
        #pragma unroll
        for (int p = 0; p < 4; p++) {
            u64 xv = xp[p];
            fma2(aq2[p], xv, wq2);
            fma2(ak2[p], xv, wk2);
            fma2(av2[p], xv, wv2);
        }
    }
    float b1 = bq[col], b2 = bk[col], b3 = bv[col];
    #pragma unroll
    for (int p = 0; p < 4; p++) {
        float q0,q1,k0,k1,v0,v1;
        upk2(aq2[p], q0, q1); upk2(ak2[p], k0, k1); upk2(av2[p], v0, v1);
        int row = row0 + rg*8 + 2*p;
        float kv0 = k0 + b2, kv1 = k1 + b2;
        g_q[row*64+col] = q0 + b1;       g_q[(row+1)*64+col] = q1 + b1;
        g_k[row*64+col] = kv0;           g_k[(row+1)*64+col] = kv1;
        g_kh[row*64+col] = __float2bfloat16(kv0);
        g_kh[(row+1)*64+col] = __float2bfloat16(kv1);
        g_v[row*64+col] = v0 + b3;       g_v[(row+1)*64+col] = v1 + b3;
    }
}

// M-score via bf16 shadow-k: 32 lanes = 4 rows x 8 heads; 16B load = one head row-slice
__global__ __launch_bounds__(256) void k_mscore(const int* __restrict__ idxs)
{
    int wid = blockIdx.x*8 + (threadIdx.x>>5);
    int lane = threadIdx.x & 31;
    int b = wid >> 13, l = wid & (LL-1);
    const int* ib = idxs + l*UU;
    int i1 = ib[lane];
    int i2 = (lane < 18) ? ib[32+lane] : 0;
    int h = lane & 7;
    int rgrp = lane >> 3;
    const float4* qp = reinterpret_cast<const float4*>(g_q + (b*LL + l)*64 + h*8);
    float4 qa = qp[0], qb_ = qp[1];
    float runmax = -INFINITY, runsum = 0.f;
    #pragma unroll
    for (int it = 0; it < 13; it++) {
        int r = it*4 + rgrp;
        int idx = (r < 32) ? __shfl_sync(0xffffffffu, i1, r)
                           : __shfl_sync(0xffffffffu, i2, r-32);
        if (r < UU) {
            uint4 raw = reinterpret_cast<const uint4*>(g_kh + (b*LL + idx)*64)[h];
            float2 f0 = __bfloat1622float2(*reinterpret_cast<__nv_bfloat162*>(&raw.x));
            float2 f1 = __bfloat1622float2(*reinterpret_cast<__nv_bfloat162*>(&raw.y));
            float2 f2 = __bfloat1622float2(*reinterpret_cast<__nv_bfloat162*>(&raw.z));
            float2 f3 = __bfloat1622float2(*reinterpret_cast<__nv_bfloat162*>(&raw.w));
            float dd = qa.x*f0.x;
            dd = fmaf(qa.y, f0.y, dd);
            dd = fmaf(qa.z, f1.x, dd);
            dd = fmaf(qa.w, f1.y, dd);
            dd = fmaf(qb_.x, f2.x, dd);
            dd = fmaf(qb_.y, f2.y, dd);
            dd = fmaf(qb_.z, f3.x, dd);
            dd = fmaf(qb_.w, f3.y, dd);
            runmax = fmaxf(runmax, dd);
            runsum += dd;
        }
    }
    runmax = fmaxf(runmax, __shfl_xor_sync(0xffffffffu, runmax, 8));
    runsum +=              __shfl_xor_sync(0xffffffffu, runsum, 8);
    runmax = fmaxf(runmax, __shfl_xor_sync(0xffffffffu, runmax, 16));
    runsum +=              __shfl_xor_sync(0xffffffffu, runsum, 16);
    if (lane < 8)
        g_M[(b*HH + h)*LL + l] = runmax - runsum * (1.0f/8192.0f);
}

// Exact top-50 as a SET via 4-pass MSB radix select
__global__ __launch_bounds__(256) void k_topk()
{
    __shared__ unsigned sK[8192];
    __shared__ int hist[256];
    __shared__ unsigned sPrefix;
    __shared__ int sRem;
    __shared__ int cnt, eqcnt;
    __shared__ int eqbuf[256];
    int bh = blockIdx.x, tid = threadIdx.x;
    const float* base = g_M + bh*LL;
    for (int i = tid; i < 8192; i += 256) sK[i] = fkey(base[i]);
    if (tid == 0) { sPrefix = 0; sRem = UU; cnt = 0; eqcnt = 0; }
    __syncthreads();
    unsigned prefmask = 0;
    #pragma unroll
    for (int pass = 0; pass < 4; pass++) {
        int shift = 24 - 8*pass;
        hist[tid] = 0;
        __syncthreads();
        unsigned pref = sPrefix;
        for (int i = tid; i < 8192; i += 256) {
            unsigned u = sK[i];
            if ((u & prefmask) == pref)
                atomicAdd(&hist[(u >> shift) & 0xffu], 1);
        }
        __syncthreads();
        if (tid == 0) {
            int acc = 0, rem = sRem;
            for (int bkt = 255; bkt >= 0; bkt--) {
                int hh = hist[bkt];
                if (acc + hh >= rem) { sPrefix = pref | ((unsigned)bkt << shift); sRem = rem - acc; break; }
                acc += hh;
            }
        }
        __syncthreads();
        prefmask |= 0xffu << shift;
    }
    unsigned T = sPrefix;
    int need = sRem;
    for (int i = tid; i < 8192; i += 256) {
        unsigned u = sK[i];
        if (u > T) {
            int p = atomicAdd(&cnt, 1);
            g_top[bh*UU + p] = i;
        } else if (u == T) {
            int p = atomicAdd(&eqcnt, 1);
            if (p < 256) eqbuf[p] = i;
        }
    }
    __syncthreads();
    if (tid == 0) {
        int basep = cnt;
        int ec = eqcnt < 256 ? eqcnt : 256;
        for (int r = 0; r < need; r++) {
            int best = 0x7fffffff, bj = 0;
            for (int j = 0; j < ec; j++)
                if (eqbuf[j] < best) { best = eqbuf[j]; bj = j; }
            eqbuf[bj] = 0x7fffffff;
            g_top[bh*UU + basep + r] = best;
        }
    }
}

__global__ void k_vpart()
{
    __shared__ float sm[4][64];
    int b = blockIdx.x >> 6, seg = blockIdx.x & 63;
    int d = threadIdx.x & 63, lg = threadIdx.x >> 6;
    const float* base = g_v + (b*LL + seg*128 + lg*32)*64 + d;
    float s = 0.f;
    #pragma unroll 8
    for (int i = 0; i < 32; i++) s += base[i*64];
    sm[lg][d] = s;
    __syncthreads();
    if (threadIdx.x < 64)
        g_vpart[(b*VSEG + seg)*64 + threadIdx.x] =
            sm[0][threadIdx.x] + sm[1][threadIdx.x] + sm[2][threadIdx.x] + sm[3][threadIdx.x];
}

__global__ void k_vmean()
{
    int t = threadIdx.x;
    int b = t >> 6, d = t & 63;
    float s = 0.f;
    #pragma unroll
    for (int i = 0; i < VSEG; i++) s += g_vpart[(b*VSEG+i)*64 + d];
    g_vmean[t] = s * (1.0f/8192.0f);
}

__global__ void k_vmc()
{
    int gid = blockIdx.x*256 + threadIdx.x;
    g_ctx[gid] = g_vmean[((gid >> 19) << 6) | (gid & 63)];
}

template<int G>
__device__ __forceinline__ void attn_group(
    int u0, int bh, int b, int h, int lane, int split,
    const float* kT, const float* vT)
{
    const float SCALE = 0.35355339059327373f;
    float4 qa[G], qb[G];
    int uu[G]; bool val[G];
    #pragma unroll
    for (int g = 0; g < G; g++) {
        int u = u0 + g*8;
        val[g] = (u < UU);
        uu[g] = val[g] ? u : 0;
        int qi = g_top[bh*UU + uu[g]];
        const float4* qp = reinterpret_cast<const float4*>(g_q + (b*LL + qi)*64 + h*8);
        qa[g] = qp[0]; qb[g] = qp[1];
    }
    float ssum[G];
    u64 pv2[G][4];
    #pragma unroll
    for (int g = 0; g < G; g++) {
        ssum[g] = 0.f;
        #pragma unroll
        for (int e = 0; e < 4; e++) pv2[g][e] = 0ull;
    }
    for (int j = lane; j < CHUNK; j += 32) {
        float k0 = kT[j],        k1 = kT[520+j],   k2 = kT[2*520+j], k3 = kT[3*520+j];
        float k4 = kT[4*520+j],  k5 = kT[5*520+j], k6 = kT[6*520+j], k7 = kT[7*520+j];
        u64 v01 = pk2(vT[j],        vT[520+j]);
        u64 v23 = pk2(vT[2*520+j],  vT[3*520+j]);
        u64 v45 = pk2(vT[4*520+j],  vT[5*520+j]);
        u64 v67 = pk2(vT[6*520+j],  vT[7*520+j]);
        #pragma unroll
        for (int g = 0; g < G; g++) {
            float s = qa[g].x*k0;
            s = fmaf(qa[g].y, k1, s);
            s = fmaf(qa[g].z, k2, s);
            s = fmaf(qa[g].w, k3, s);
            s = fmaf(qb[g].x, k4, s);
            s = fmaf(qb[g].y, k5, s);
            s = fmaf(qb[g].z, k6, s);
            s = fmaf(qb[g].w, k7, s);
            float p = __expf(s * SCALE);
            ssum[g] += p;
            u64 p2 = pk2(p, p);
            fma2(pv2[g][0], v01, p2);
            fma2(pv2[g][1], v23, p2);
            fma2(pv2[g][2], v45, p2);
            fma2(pv2[g][3], v67, p2);
        }
    }
    #pragma unroll
    for (int g = 0; g < G; g++) {
        float pv[8];
        #pragma unroll
        for (int e = 0; e < 4; e++) upk2(pv2[g][e], pv[2*e], pv[2*e+1]);
        #pragma unroll
        for (int o = 16; o; o >>= 1) {
            ssum[g] += __shfl_xor_sync(0xffffffffu, ssum[g], o);
            #pragma unroll
            for (int e = 0; e < 8; e++) pv[e] += __shfl_xor_sync(0xffffffffu, pv[e], o);
        }
        if (lane == 0 && val[g]) {
            float* pp = g_part + ((bh*UU + uu[g])*NSPLIT + split)*10;
            #pragma unroll
            for (int e = 0; e < 8; e++) pp[e] = pv[e];
            pp[8] = ssum[g];
        }
    }
}

__global__ __launch_bounds__(256) void k_attn()
{
    __shared__ float kT[8*520];
    __shared__ float vT[8*520];
    int bh = blockIdx.x >> 4, split = blockIdx.x & 15;
    int b = bh >> 3, h = bh & 7;
    int l0 = split * CHUNK, tid = threadIdx.x;
    for (int i = tid; i < CHUNK*8; i += 256) {
        int j = i >> 3, e = i & 7;
        int g = (b*LL + l0 + j)*64 + h*8 + e;
        kT[e*520 + j] = g_k[g];
        vT[e*520 + j] = g_v[g];
    }
    __syncthreads();
    int w = tid >> 5, lane = tid & 31;
    attn_group<4>(w,      bh, b, h, lane, split, kT, vT);
    attn_group<3>(w + 32, bh, b, h, lane, split, kT, vT);
}

__global__ void k_merge()
{
    int gid = blockIdx.x*256 + threadIdx.x;
    int e = gid & 7, rest = gid >> 3;
    int u = rest % UU, bh = rest / UU;
    int b = bh >> 3, h = bh & 7;
    const float* pp = g_part + ((bh*UU + u)*NSPLIT)*10;
    float pv = 0.f, ss = 0.f;
    for (int s = 0; s < NSPLIT; s++) { pv += pp[s*10 + e]; ss += pp[s*10 + 8]; }
    int qi = g_top[bh*UU + u];
    g_ctx[(b*LL + qi)*64 + h*8 + e] = pv / ss;
}

__device__ __forceinline__ void ln_epilogue(float* out65, int row0, int tid,
    const float* __restrict__ lg, const float* __restrict__ lb)
{
    int w = tid >> 5, lane = tid & 31;
    float gg0 = lg[lane], gg1 = lg[lane+32], bb0 = lb[lane], bb1 = lb[lane+32];
    #pragma unroll
    for (int rr = 0; rr < 4; rr++) {
        int r = w*4 + rr;
        float v0 = out65[r*65 + lane], v1 = out65[r*65 + lane + 32];
        float s = v0 + v1;
        #pragma unroll
        for (int o = 16; o; o >>= 1) s += __shfl_xor_sync(0xffffffffu, s, o);
        float mean = s * (1.0f/64.0f);
        float d0 = v0 - mean, d1 = v1 - mean;
        float s2 = d0*d0 + d1*d1;
        #pragma unroll
        for (int o = 16; o; o >>= 1) s2 += __shfl_xor_sync(0xffffffffu, s2, o);
        float inv = rsqrtf(s2 * (1.0f/64.0f) + 1e-5f);
        int go = (row0 + r)*64;
        g_x[go + lane]      = fmaf(d0 * inv, gg0, bb0);
        g_x[go + lane + 32] = fmaf(d1 * inv, gg1, bb1);
    }
}

__global__ __launch_bounds__(256) void k_wo_ln(
    const u64* __restrict__ W, const float* __restrict__ bo,
    const float* __restrict__ lg, const float* __restrict__ lb)
{
    __shared__ __align__(16) float xT[64*36];
    __shared__ float out[32*65];
    int row0 = blockIdx.x * 32, tid = threadIdx.x;
    for (int i = tid; i < 2048; i += 256) { int c=i&63, r=i>>6; xT[c*36+r] = g_ctx[(row0+r)*64+c]; }
    __syncthreads();
    int col = tid & 63, rg = tid >> 6;
    u64 acc2[4];
    #pragma unroll
    for (int p = 0; p < 4; p++) acc2[p] = 0ull;
    #pragma unroll 4
    for (int kk = 0; kk < 64; kk++) {
        u64 w2 = W[kk*64+col];
        const u64* xp = reinterpret_cast<const u64*>(&xT[kk*36 + rg*8]);
        #pragma unroll
        for (int p = 0; p < 4; p++) fma2(acc2[p], xp[p], w2);
    }
    float bv2 = bo[col];
    #pragma unroll
    for (int p = 0; p < 4; p++) {
        float f0, f1;
        upk2(acc2[p], f0, f1);
        int r = rg*8 + 2*p;
        out[r*65 + col]     = f0 + bv2 + g_x[(row0 + r)*64 + col];
        out[(r+1)*65 + col] = f1 + bv2 + g_x[(row0 + r + 1)*64 + col];
    }
    __syncthreads();
    ln_epilogue(out, row0, tid, lg, lb);
}

__global__ __launch_bounds__(256) void k_ffn(
    const u64* __restrict__ W1, const float* __restrict__ b1,
    const u64* __restrict__ W2, const float* __restrict__ b2,
    const float* __restrict__ lg, const float* __restrict__ lb)
{
    __shared__ __align__(16) float yT[256*36];
    __shared__ __align__(16) float xTo[64*36];
    int row0 = blockIdx.x * 32, tid = threadIdx.x;
    for (int i = tid; i < 2048; i += 256) { int c=i&63, r=i>>6; xTo[c*36+r] = g_x[(row0+r)*64+c]; }
    __syncthreads();
    int col = tid & 63, rg = tid >> 6;
    u64 acc2[16];
    #pragma unroll
    for (int i = 0; i < 16; i++) acc2[i] = 0ull;
    #pragma unroll 2
    for (int kk = 0; kk < 64; kk++) {
        u64 w0 = W1[kk*256 + col];
        u64 w1 = W1[kk*256 + 64 + col];
        u64 w2 = W1[kk*256 + 128 + col];
        u64 w3 = W1[kk*256 + 192 + col];
        const u64* xp = reinterpret_cast<const u64*>(&xTo[kk*36 + rg*8]);
        #pragma unroll
        for (int p = 0; p < 4; p++) {
            u64 xv = xp[p];
            fma2(acc2[p],    xv, w0);
            fma2(acc2[4+p],  xv, w1);
            fma2(acc2[8+p],  xv, w2);
            fma2(acc2[12+p], xv, w3);
        }
    }
    __syncthreads();
    #pragma unroll
    for (int t = 0; t < 4; t++) {
        float bb = b1[t*64 + col];
        float f[8];
        #pragma unroll
        for (int p = 0; p < 4; p++) {
            float a, c;
            upk2(acc2[t*4+p], a, c);
            f[2*p]   = fmaxf(a + bb, 0.f);
            f[2*p+1] = fmaxf(c + bb, 0.f);
        }
        float4 f0 = {f[0], f[1], f[2], f[3]};
        float4 f1 = {f[4], f[5], f[6], f[7]};
        *reinterpret_cast<float4*>(&yT[(t*64+col)*36 + rg*8])     = f0;
        *reinterpret_cast<float4*>(&yT[(t*64+col)*36 + rg*8 + 4]) = f1;
    }
    __syncthreads();
    u64 a2[4];
    #pragma unroll
    for (int p = 0; p < 4; p++) a2[p] = 0ull;
    #pragma unroll 4
    for (int kk = 0; kk < 256; kk++) {
        u64 w2 = W2[kk*64 + col];
        const u64* yp = reinterpret_cast<const u64*>(&yT[kk*36 + rg*8]);
        #pragma unroll
        for (int p = 0; p < 4; p++) fma2(a2[p], yp[p], w2);
    }
    float bv2 = b2[col];
    float* out = xTo;
    #pragma unroll
    for (int p = 0; p < 4; p++) {
        float f0, f1;
        upk2(a2[p], f0, f1);
        int r = rg*8 + 2*p;
        out[r*65 + col]     = f0 + bv2 + g_x[(row0 + r)*64 + col];
        out[(r+1)*65 + col] = f1 + bv2 + g_x[(row0 + r + 1)*64 + col];
    }
    __syncthreads();
    ln_epilogue(out, row0, tid, lg, lb);
}

__global__ __launch_bounds__(256) void k_final(
    const float* __restrict__ lg, const float* __restrict__ lb,
    const float* __restrict__ pw, const float* __restrict__ pb,
    float* __restrict__ outp)
{
    int row = blockIdx.x*8 + (threadIdx.x >> 5);
    int lane = threadIdx.x & 31;
    const float* xr = g_x + row*64;
    float v0 = xr[lane], v1 = xr[lane+32];
    float s = v0 + v1;
    #pragma unroll
    for (int o = 16; o; o >>= 1) s += __shfl_xor_sync(0xffffffffu, s, o);
    float mean = s * (1.0f/64.0f);
    float d0 = v0 - mean, d1 = v1 - mean;
    float s2 = d0*d0 + d1*d1;
    #pragma unroll
    for (int o = 16; o; o >>= 1) s2 += __shfl_xor_sync(0xffffffffu, s2, o);
    float inv = rsqrtf(s2 * (1.0f/64.0f) + 1e-5f);
    float xn0 = fmaf(d0 * inv, lg[lane],    lb[lane]);
    float xn1 = fmaf(d1 * inv, lg[lane+32], lb[lane+32]);
    float lgt[5];
    #pragma unroll
    for (int c = 0; c < 5; c++) {
        float t = fmaf(xn0, pw[lane*5 + c], xn1 * pw[(lane+32)*5 + c]);
        #pragma unroll
        for (int o = 16; o; o >>= 1) t += __shfl_xor_sync(0xffffffffu, t, o);
        lgt[c] = t + pb[c];
    }
    float m = lgt[0];
    #pragma unroll
    for (int c = 1; c < 5; c++) m = fmaxf(m, lgt[c]);
    float e[5], se = 0.f;
    #pragma unroll
    for (int c = 0; c < 5; c++) { e[c] = __expf(lgt[c] - m); se += e[c]; }
    float rse = 1.0f / se;
    if (lane == 0) {
        #pragma unroll
        for (int c = 0; c < 5; c++) outp[row*5 + c] = e[c] * rse;
    }
}

extern "C" void kernel_launch(void* const* d_in, const int* in_sizes, int n_in,
                              void* d_out, int out_size)
{
    const float* x_enc   = (const float*)d_in[0];
    const int*   idxs    = (const int*)  d_in[1];
    const float* emb_w   = (const float*)d_in[2];
    const float* Wq      = (const float*)d_in[3];
    const float* bq      = (const float*)d_in[4];
    const float* Wk      = (const float*)d_in[5];
    const float* bk      = (const float*)d_in[6];
    const float* Wv      = (const float*)d_in[7];
    const float* bv      = (const float*)d_in[8];
    const float* Wo      = (const float*)d_in[9];
    const float* bo      = (const float*)d_in[10];
    const float* c1w     = (const float*)d_in[11];
    const float* c1b     = (const float*)d_in[12];
    const float* c2w     = (const float*)d_in[13];
    const float* c2b     = (const float*)d_in[14];
    const float* ln1g    = (const float*)d_in[15];
    const float* ln1b    = (const float*)d_in[16];
    const float* ln2g    = (const float*)d_in[17];
    const float* ln2b    = (const float*)d_in[18];
    const float* lnfg    = (const float*)d_in[19];
    const float* lnfb    = (const float*)d_in[20];
    const float* projw   = (const float*)d_in[21];
    const float* projb   = (const float*)d_in[22];
    float* outp = (float*)d_out;

    cudaStream_t s1;
    cudaStreamCreateWithFlags(&s1, cudaStreamNonBlocking);
    cudaEvent_t evS, evP, evF[2], evJ[2];
    cudaEventCreateWithFlags(&evS, cudaEventDisableTiming);
    cudaEventCreateWithFlags(&evP, cudaEventDisableTiming);
    for (int i = 0; i < 2; i++) {
        cudaEventCreateWithFlags(&evF[i], cudaEventDisableTiming);
        cudaEventCreateWithFlags(&evJ[i], cudaEventDisableTiming);
    }

    u64 *wqp, *wkp, *wvp, *wop, *w1p, *w2p;
    cudaGetSymbolAddress((void**)&wqp, g_wqp);
    cudaGetSymbolAddress((void**)&wkp, g_wkp);
    cudaGetSymbolAddress((void**)&wvp, g_wvp);
    cudaGetSymbolAddress((void**)&wop, g_wop);
    cudaGetSymbolAddress((void**)&w1p, g_w1p);
    cudaGetSymbolAddress((void**)&w2p, g_w2p);

    // capture-safe fork: first node on capturing stream, then fork s1 via event
    k_div<<<1, 32>>>();
    cudaEventRecord(evS, 0);
    cudaStreamWaitEvent(s1, evS, 0);
    k_packall<<<384, 256, 0, s1>>>(Wq, Wk, Wv, Wo, c1w, c2w);  // one kernel, ~5us, hides under embed
    cudaEventRecord(evP, s1);

    k_embed<<<ROWS*DM/256, 256>>>(x_enc, emb_w);
    cudaStreamWaitEvent(0, evP, 0);   // packed weights ready before first GEMM

    for (int i = 0; i < 2; i++) {
        k_qkv<<<ROWS/32, 256>>>(wqp + i*DM*DM, bq + i*DM, wkp + i*DM*DM, bk + i*DM,
                                wvp + i*DM*DM, bv + i*DM);
        cudaEventRecord(evF[i], 0);
        cudaStreamWaitEvent(s1, evF[i], 0);
        k_vpart<<<BB*VSEG, 256, 0, s1>>>();
        k_vmean<<<1, BB*DM, 0, s1>>>();
        k_vmc<<<ROWS*DM/256, 256, 0, s1>>>();
        cudaEventRecord(evJ[i], s1);
        k_mscore<<<ROWS/8, 256>>>(idxs + i*LL*UU);
        k_topk<<<BB*HH, 256>>>();
        k_attn<<<BB*HH*NSPLIT, 256>>>();
        cudaStreamWaitEvent(0, evJ[i], 0);
        k_merge<<<BB*HH*UU*8/256, 256>>>();
        k_wo_ln<<<ROWS/32, 256>>>(wop + i*DM*DM, bo + i*DM, ln1g + i*DM, ln1b + i*DM);
        k_ffn<<<ROWS/32, 256>>>(w1p + i*DM*DFF, c1b + i*DFF, w2p + i*DFF*DM, c2b + i*DM,
                                ln2g + i*DM, ln2b + i*DM);
    }
    k_final<<<ROWS/8, 256>>>(lnfg, lnfb, projw, projb, outp);
}

// round 14
// speedup vs baseline: 1.0657x; 1.0570x over previous
#include <cuda_runtime.h>
#include <cuda_bf16.h>
#include <math.h>
#include <stdint.h>

#define BB 4
#define LL 8192
#define DM 64
#define HH 8
#define DFF 256
#define UU 50
#define ROWS (BB*LL)
#define CHUNK 512
#define NSPLIT 16
#define VSEG 64

typedef unsigned long long u64;

__device__ __align__(16) float g_x[ROWS*DM];
__device__ __align__(16) float g_q[ROWS*DM];
__device__ __align__(16) float g_k[ROWS*DM];
__device__ __align__(16) float g_v[ROWS*DM];
__device__ __align__(16) __nv_bfloat16 g_kh[ROWS*DM];
__device__ __align__(16) float g_ctx[ROWS*DM];
__device__ float g_M[BB*HH*LL];
__device__ int   g_top[BB*HH*UU];
__device__ float g_vpart[BB*VSEG*DM];
__device__ float g_vmean[BB*DM];
__device__ float g_part[BB*HH*UU*NSPLIT*10];
__device__ float2 g_div[32];

// ---- packed fp32x2 helpers (bit-exact: each half is an IEEE fp32 FMA) ----
__device__ __forceinline__ u64 pk2(float lo, float hi) {
    u64 r;
    asm("mov.b64 %0, {%1, %2};" : "=l"(r) : "r"(__float_as_uint(lo)), "r"(__float_as_uint(hi)));
    return r;
}
__device__ __forceinline__ void upk2(u64 v, float &lo, float &hi) {
    unsigned a, b;
    asm("mov.b64 {%0, %1}, %2;" : "=r"(a), "=r"(b) : "l"(v));
    lo = __uint_as_float(a); hi = __uint_as_float(b);
}
__device__ __forceinline__ void fma2(u64 &d, u64 a, u64 b) {
    asm("fma.rn.f32x2 %0, %1, %2, %0;" : "+l"(d) : "l"(a), "l"(b));
}

__device__ __forceinline__ unsigned fkey(float f) {
    unsigned u = __float_as_uint(f);
    return (u & 0x80000000u) ? ~u : (u | 0x80000000u);
}

__global__ void k_div() {
    int i = threadIdx.x;
    double dvd = exp(((double)(-2*i)) * (log(10000.0) / 64.0));
    float hi = (float)dvd;
    g_div[i] = make_float2(hi, (float)(dvd - (double)hi));
}

__global__ void k_embed(const float* __restrict__ xe, const float* __restrict__ ew) {
    int gid = blockIdx.x*256 + threadIdx.x;
    int d = gid & 63, row = gid >> 6;
    int l = row & (LL-1), b = row >> 13;
    const float* xb = xe + b*LL;
    float tok = ew[d*3+0]*xb[(l+LL-1)&(LL-1)] + ew[d*3+1]*xb[l] + ew[d*3+2]*xb[(l+1)&(LL-1)];
    float2 dv = g_div[d >> 1];
    float lf = (float)l;
    float ph = lf * dv.x;
    float perr = fmaf(lf, dv.x, -ph);
    float plo = fmaf(lf, dv.y, perr);
    float kq = rintf(ph * 0.63661977236758134f);
    float r = fmaf(-kq, 1.57079637050628662109375f, ph);
    r = fmaf(kq, 4.37113900018624283e-08f, r);
    r += plo;
    int qd = (((int)kq) + (d & 1)) & 3;
    float sr = sinf(r), cr = cosf(r);
    float pe = (qd == 0) ? sr : (qd == 1) ? cr : (qd == 2) ? -sr : -cr;
    g_x[gid] = tok + pe;
}

// QKV: one matrix per block (blockIdx.y in {0:q, 1:k, 2:v}) — low regs, high occupancy.
// Accumulation chains identical to the fused version -> bit-exact.
__global__ __launch_bounds__(256) void k_qkv(
    const float* __restrict__ Wq, const float* __restrict__ bq,
    const float* __restrict__ Wk, const float* __restrict__ bk,
    const float* __restrict__ Wv, const float* __restrict__ bv)
{
    __shared__ __align__(16) float xT[64*36];
    int row0 = blockIdx.x * 32, tid = threadIdx.x;
    int m = blockIdx.y;
    const float* W    = (m == 0) ? Wq : (m == 1) ? Wk : Wv;
    const float* bias = (m == 0) ? bq : (m == 1) ? bk : bv;
    for (int i = tid; i < 2048; i += 256) { int c=i&63, r=i>>6; xT[c*36+r] = g_x[(row0+r)*64+c]; }
    __syncthreads();
    int col = tid & 63, rg = tid >> 6;
    u64 acc2[4];
    #pragma unroll
    for (int p = 0; p < 4; p++) acc2[p] = 0ull;
    #pragma unroll 4
    for (int kk = 0; kk < 64; kk++) {
        float wv = W[kk*64+col];
        u64 w2 = pk2(wv, wv);
        const u64* xp = reinterpret_cast<const u64*>(&xT[kk*36 + rg*8]);
        #pragma unroll
        for (int p = 0; p < 4; p++) fma2(acc2[p], xp[p], w2);
    }
    float bb = bias[col];
    #pragma unroll
    for (int p = 0; p < 4; p++) {
        float f0, f1;
        upk2(acc2[p], f0, f1);
        int row = row0 + rg*8 + 2*p;
        f0 += bb; f1 += bb;
        if (m == 0) {
            g_q[row*64+col] = f0;        g_q[(row+1)*64+col] = f1;
        } else if (m == 1) {
            g_k[row*64+col] = f0;        g_k[(row+1)*64+col] = f1;
            g_kh[row*64+col] = __float2bfloat16(f0);
            g_kh[(row+1)*64+col] = __float2bfloat16(f1);
        } else {
            g_v[row*64+col] = f0;        g_v[(row+1)*64+col] = f1;
        }
    }
}

// M-score via bf16 shadow-k: 32 lanes = 4 rows x 8 heads; 16B load = one head row-slice
__global__ __launch_bounds__(256) void k_mscore(const int* __restrict__ idxs)
{
    int wid = blockIdx.x*8 + (threadIdx.x>>5);
    int lane = threadIdx.x & 31;
    int b = wid >> 13, l = wid & (LL-1);
    const int* ib = idxs + l*UU;
    int i1 = ib[lane];
    int i2 = (lane < 18) ? ib[32+lane] : 0;
    int h = lane & 7;
    int rgrp = lane >> 3;
    const float4* qp = reinterpret_cast<const float4*>(g_q + (b*LL + l)*64 + h*8);
    float4 qa = qp[0], qb_ = qp[1];
    float runmax = -INFINITY, runsum = 0.f;
    #pragma unroll
    for (int it = 0; it < 13; it++) {
        int r = it*4 + rgrp;
        int idx = (r < 32) ? __shfl_sync(0xffffffffu, i1, r)
                           : __shfl_sync(0xffffffffu, i2, r-32);
        if (r < UU) {
            uint4 raw = reinterpret_cast<const uint4*>(g_kh + (b*LL + idx)*64)[h];
            float2 f0 = __bfloat1622float2(*reinterpret_cast<__nv_bfloat162*>(&raw.x));
            float2 f1 = __bfloat1622float2(*reinterpret_cast<__nv_bfloat162*>(&raw.y));
            float2 f2 = __bfloat1622float2(*reinterpret_cast<__nv_bfloat162*>(&raw.z));
            float2 f3 = __bfloat1622float2(*reinterpret_cast<__nv_bfloat162*>(&raw.w));
            float dd = qa.x*f0.x;
            dd = fmaf(qa.y, f0.y, dd);
            dd = fmaf(qa.z, f1.x, dd);
            dd = fmaf(qa.w, f1.y, dd);
            dd = fmaf(qb_.x, f2.x, dd);
            dd = fmaf(qb_.y, f2.y, dd);
            dd = fmaf(qb_.z, f3.x, dd);
            dd = fmaf(qb_.w, f3.y, dd);
            runmax = fmaxf(runmax, dd);
            runsum += dd;
        }
    }
    runmax = fmaxf(runmax, __shfl_xor_sync(0xffffffffu, runmax, 8));
    runsum +=              __shfl_xor_sync(0xffffffffu, runsum, 8);
    runmax = fmaxf(runmax, __shfl_xor_sync(0xffffffffu, runmax, 16));
    runsum +=              __shfl_xor_sync(0xffffffffu, runsum, 16);
    if (lane < 8)
        g_M[(b*HH + h)*LL + l] = runmax - runsum * (1.0f/8192.0f);
}

// Exact top-50 as a SET via 4-pass MSB radix select
__global__ __launch_bounds__(256) void k_topk()
{
    __shared__ unsigned sK[8192];
    __shared__ int hist[256];
    __shared__ unsigned sPrefix;
    __shared__ int sRem;
    __shared__ int cnt, eqcnt;
    __shared__ int eqbuf[256];
    int bh = blockIdx.x, tid = threadIdx.x;
    const float* base = g_M + bh*LL;
    for (int i = tid; i < 8192; i += 256) sK[i] = fkey(base[i]);
    if (tid == 0) { sPrefix = 0; sRem = UU; cnt = 0; eqcnt = 0; }
    __syncthreads();
    unsigned prefmask = 0;
    #pragma unroll
    for (int pass = 0; pass < 4; pass++) {
        int shift = 24 - 8*pass;
        hist[tid] = 0;
        __syncthreads();
        unsigned pref = sPrefix;
        for (int i = tid; i < 8192; i += 256) {
            unsigned u = sK[i];
            if ((u & prefmask) == pref)
                atomicAdd(&hist[(u >> shift) & 0xffu], 1);
        }
        __syncthreads();
        if (tid == 0) {
            int acc = 0, rem = sRem;
            for (int bkt = 255; bkt >= 0; bkt--) {
                int hh = hist[bkt];
                if (acc + hh >= rem) { sPrefix = pref | ((unsigned)bkt << shift); sRem = rem - acc; break; }
                acc += hh;
            }
        }
        __syncthreads();
        prefmask |= 0xffu << shift;
    }
    unsigned T = sPrefix;
    int need = sRem;
    for (int i = tid; i < 8192; i += 256) {
        unsigned u = sK[i];
        if (u > T) {
            int p = atomicAdd(&cnt, 1);
            g_top[bh*UU + p] = i;
        } else if (u == T) {
            int p = atomicAdd(&eqcnt, 1);
            if (p < 256) eqbuf[p] = i;
        }
    }
    __syncthreads();
    if (tid == 0) {
        int basep = cnt;
        int ec = eqcnt < 256 ? eqcnt : 256;
        for (int r = 0; r < need; r++) {
            int best = 0x7fffffff, bj = 0;
            for (int j = 0; j < ec; j++)
                if (eqbuf[j] < best) { best = eqbuf[j]; bj = j; }
            eqbuf[bj] = 0x7fffffff;
            g_top[bh*UU + basep + r] = best;
        }
    }
}

__global__ void k_vpart()
{
    __shared__ float sm[4][64];
    int b = blockIdx.x >> 6, seg = blockIdx.x & 63;
    int d = threadIdx.x & 63, lg = threadIdx.x >> 6;
    const float* base = g_v + (b*LL + seg*128 + lg*32)*64 + d;
    float s = 0.f;
    #pragma unroll 8
    for (int i = 0; i < 32; i++) s += base[i*64];
    sm[lg][d] = s;
    __syncthreads();
    if (threadIdx.x < 64)
        g_vpart[(b*VSEG + seg)*64 + threadIdx.x] =
            sm[0][threadIdx.x] + sm[1][threadIdx.x] + sm[2][threadIdx.x] + sm[3][threadIdx.x];
}

__global__ void k_vmean()
{
    int t = threadIdx.x;
    int b = t >> 6, d = t & 63;
    float s = 0.f;
    #pragma unroll
    for (int i = 0; i < VSEG; i++) s += g_vpart[(b*VSEG+i)*64 + d];
    g_vmean[t] = s * (1.0f/8192.0f);
}

__global__ void k_vmc()
{
    int gid = blockIdx.x*256 + threadIdx.x;
    g_ctx[gid] = g_vmean[((gid >> 19) << 6) | (gid & 63)];
}

template<int G>
__device__ __forceinline__ void attn_group(
    int u0, int bh, int b, int h, int lane, int split,
    const float* kT, const float* vT)
{
    const float SCALE = 0.35355339059327373f;
    float4 qa[G], qb[G];
    int uu[G]; bool val[G];
    #pragma unroll
    for (int g = 0; g < G; g++) {
        int u = u0 + g*8;
        val[g] = (u < UU);
        uu[g] = val[g] ? u : 0;
        int qi = g_top[bh*UU + uu[g]];
        const float4* qp = reinterpret_cast<const float4*>(g_q + (b*LL + qi)*64 + h*8);
        qa[g] = qp[0]; qb[g] = qp[1];
    }
    float ssum[G];
    u64 pv2[G][4];
    #pragma unroll
    for (int g = 0; g < G; g++) {
        ssum[g] = 0.f;
        #pragma unroll
        for (int e = 0; e < 4; e++) pv2[g][e] = 0ull;
    }
    for (int j = lane; j < CHUNK; j += 32) {
        float k0 = kT[j],        k1 = kT[520+j],   k2 = kT[2*520+j], k3 = kT[3*520+j];
        float k4 = kT[4*520+j],  k5 = kT[5*520+j], k6 = kT[6*520+j], k7 = kT[7*520+j];
        u64 v01 = pk2(vT[j],        vT[520+j]);
        u64 v23 = pk2(vT[2*520+j],  vT[3*520+j]);
        u64 v45 = pk2(vT[4*520+j],  vT[5*520+j]);
        u64 v67 = pk2(vT[6*520+j],  vT[7*520+j]);
        #pragma unroll
        for (int g = 0; g < G; g++) {
            float s = qa[g].x*k0;
            s = fmaf(qa[g].y, k1, s);
            s = fmaf(qa[g].z, k2, s);
            s = fmaf(qa[g].w, k3, s);
            s = fmaf(qb[g].x, k4, s);
            s = fmaf(qb[g].y, k5, s);
            s = fmaf(qb[g].z, k6, s);
            s = fmaf(qb[g].w, k7, s);
            float p = __expf(s * SCALE);
            ssum[g] += p;
            u64 p2 = pk2(p, p);
            fma2(pv2[g][0], v01, p2);
            fma2(pv2[g][1], v23, p2);
            fma2(pv2[g][2], v45, p2);
            fma2(pv2[g][3], v67, p2);
        }
    }
    #pragma unroll
    for (int g = 0; g < G; g++) {
        float pv[8];
        #pragma unroll
        for (int e = 0; e < 4; e++) upk2(pv2[g][e], pv[2*e], pv[2*e+1]);
        #pragma unroll
        for (int o = 16; o; o >>= 1) {
            ssum[g] += __shfl_xor_sync(0xffffffffu, ssum[g], o);
            #pragma unroll
            for (int e = 0; e < 8; e++) pv[e] += __shfl_xor_sync(0xffffffffu, pv[e], o);
        }
        if (lane == 0 && val[g]) {
            float* pp = g_part + ((bh*UU + uu[g])*NSPLIT + split)*10;
            #pragma unroll
            for (int e = 0; e < 8; e++) pp[e] = pv[e];
            pp[8] = ssum[g];
        }
    }
}

__global__ __launch_bounds__(256) void k_attn()
{
    __shared__ float kT[8*520];
    __shared__ float vT[8*520];
    int bh = blockIdx.x >> 4, split = blockIdx.x & 15;
    int b = bh >> 3, h = bh & 7;
    int l0 = split * CHUNK, tid = threadIdx.x;
    for (int i = tid; i < CHUNK*8; i += 256) {
        int j = i >> 3, e = i & 7;
        int g = (b*LL + l0 + j)*64 + h*8 + e;
        kT[e*520 + j] = g_k[g];
        vT[e*520 + j] = g_v[g];
    }
    __syncthreads();
    int w = tid >> 5, lane = tid & 31;
    attn_group<4>(w,      bh, b, h, lane, split, kT, vT);
    attn_group<3>(w + 32, bh, b, h, lane, split, kT, vT);
}

__global__ void k_merge()
{
    int gid = blockIdx.x*256 + threadIdx.x;
    int e = gid & 7, rest = gid >> 3;
    int u = rest % UU, bh = rest / UU;
    int b = bh >> 3, h = bh & 7;
    const float* pp = g_part + ((bh*UU + u)*NSPLIT)*10;
    float pv = 0.f, ss = 0.f;
    for (int s = 0; s < NSPLIT; s++) { pv += pp[s*10 + e]; ss += pp[s*10 + 8]; }
    int qi = g_top[bh*UU + u];
    g_ctx[(b*LL + qi)*64 + h*8 + e] = pv / ss;
}

__device__ __forceinline__ void ln_epilogue(float* out65, int row0, int tid,
    const float* __restrict__ lg, const float* __restrict__ lb)
{
    int w = tid >> 5, lane = tid & 31;
    float gg0 = lg[lane], gg1 = lg[lane+32], bb0 = lb[lane], bb1 = lb[lane+32];
    #pragma unroll
    for (int rr = 0; rr < 4; rr++) {
        int r = w*4 + rr;
        float v0 = out65[r*65 + lane], v1 = out65[r*65 + lane + 32];
        float s = v0 + v1;
        #pragma unroll
        for (int o = 16; o; o >>= 1) s += __shfl_xor_sync(0xffffffffu, s, o);
        float mean = s * (1.0f/64.0f);
        float d0 = v0 - mean, d1 = v1 - mean;
        float s2 = d0*d0 + d1*d1;
        #pragma unroll
        for (int o = 16; o; o >>= 1) s2 += __shfl_xor_sync(0xffffffffu, s2, o);
        float inv = rsqrtf(s2 * (1.0f/64.0f) + 1e-5f);
        int go = (row0 + r)*64;
        g_x[go + lane]      = fmaf(d0 * inv, gg0, bb0);
        g_x[go + lane + 32] = fmaf(d1 * inv, gg1, bb1);
    }
}

__global__ __launch_bounds__(256) void k_wo_ln(
    const float* __restrict__ W, const float* __restrict__ bo,
    const float* __restrict__ lg, const float* __restrict__ lb)
{
    __shared__ __align__(16) float xT[64*36];
    __shared__ float out[32*65];
    int row0 = blockIdx.x * 32, tid = threadIdx.x;
    for (int i = tid; i < 2048; i += 256) { int c=i&63, r=i>>6; xT[c*36+r] = g_ctx[(row0+r)*64+c]; }
    __syncthreads();
    int col = tid & 63, rg = tid >> 6;
    u64 acc2[4];
    #pragma unroll
    for (int p = 0; p < 4; p++) acc2[p] = 0ull;
    #pragma unroll 4
    for (int kk = 0; kk < 64; kk++) {
        float wvv = W[kk*64+col];
        u64 w2 = pk2(wvv, wvv);
        const u64* xp = reinterpret_cast<const u64*>(&xT[kk*36 + rg*8]);
        #pragma unroll
        for (int p = 0; p < 4; p++) fma2(acc2[p], xp[p], w2);
    }
    float bv2 = bo[col];
    #pragma unroll
    for (int p = 0; p < 4; p++) {
        float f0, f1;
        upk2(acc2[p], f0, f1);
        int r = rg*8 + 2*p;
        out[r*65 + col]     = f0 + bv2 + g_x[(row0 + r)*64 + col];
        out[(r+1)*65 + col] = f1 + bv2 + g_x[(row0 + r + 1)*64 + col];
    }
    __syncthreads();
    ln_epilogue(out, row0, tid, lg, lb);
}

__global__ __launch_bounds__(256) void k_ffn(
    const float* __restrict__ W1, const float* __restrict__ b1,
    const float* __restrict__ W2, const float* __restrict__ b2,
    const float* __restrict__ lg, const float* __restrict__ lb)
{
    __shared__ __align__(16) float yT[256*36];
    __shared__ __align__(16) float xTo[64*36];
    int row0 = blockIdx.x * 32, tid = threadIdx.x;
    for (int i = tid; i < 2048; i += 256) { int c=i&63, r=i>>6; xTo[c*36+r] = g_x[(row0+r)*64+c]; }
    __syncthreads();
    int col = tid & 63, rg = tid >> 6;
    u64 acc2[16];
    #pragma unroll
    for (int i = 0; i < 16; i++) acc2[i] = 0ull;
    #pragma unroll 2
    for (int kk = 0; kk < 64; kk++) {
        u64 w0 = pk2(W1[kk*256 + col],       W1[kk*256 + col]);
        u64 w1 = pk2(W1[kk*256 + 64 + col],  W1[kk*256 + 64 + col]);
        u64 w2 = pk2(W1[kk*256 + 128 + col], W1[kk*256 + 128 + col]);
        u64 w3 = pk2(W1[kk*256 + 192 + col], W1[kk*256 + 192 + col]);
        const u64* xp = reinterpret_cast<const u64*>(&xTo[kk*36 + rg*8]);
        #pragma unroll
        for (int p = 0; p < 4; p++) {
            u64 xv = xp[p];
            fma2(acc2[p],    xv, w0);
            fma2(acc2[4+p],  xv, w1);
            fma2(acc2[8+p],  xv, w2);
            fma2(acc2[12+p], xv, w3);
        }
    }
    __syncthreads();
    #pragma unroll
    for (int t = 0; t < 4; t++) {
        float bb = b1[t*64 + col];
        float f[8];
        #pragma unroll
        for (int p = 0; p < 4; p++) {
            float a, c;
            upk2(acc2[t*4+p], a, c);
            f[2*p]   = fmaxf(a + bb, 0.f);
            f[2*p+1] = fmaxf(c + bb, 0.f);
        }
        float4 f0 = {f[0], f[1], f[2], f[3]};
        float4 f1 = {f[4], f[5], f[6], f[7]};
        *reinterpret_cast<float4*>(&yT[(t*64+col)*36 + rg*8])     = f0;
        *reinterpret_cast<float4*>(&yT[(t*64+col)*36 + rg*8 + 4]) = f1;
    }
    __syncthreads();
    u64 a2[4];
    #pragma unroll
    for (int p = 0; p < 4; p++) a2[p] = 0ull;
    #pragma unroll 4
    for (int kk = 0; kk < 256; kk++) {
        float wvv = W2[kk*64 + col];
        u64 w2 = pk2(wvv, wvv);
        const u64* yp = reinterpret_cast<const u64*>(&yT[kk*36 + rg*8]);
        #pragma unroll
        for (int p = 0; p < 4; p++) fma2(a2[p], yp[p], w2);
    }
    float bv2 = b2[col];
    float* out = xTo;
    #pragma unroll
    for (int p = 0; p < 4; p++) {
        float f0, f1;
        upk2(a2[p], f0, f1);
        int r = rg*8 + 2*p;
        out[r*65 + col]     = f0 + bv2 + g_x[(row0 + r)*64 + col];
        out[(r+1)*65 + col] = f1 + bv2 + g_x[(row0 + r + 1)*64 + col];
    }
    __syncthreads();
    ln_epilogue(out, row0, tid, lg, lb);
}

__global__ __launch_bounds__(256) void k_final(
    const float* __restrict__ lg, const float* __restrict__ lb,
    const float* __restrict__ pw, const float* __restrict__ pb,
    float* __restrict__ outp)
{
    int row = blockIdx.x*8 + (threadIdx.x >> 5);
    int lane = threadIdx.x & 31;
    const float* xr = g_x + row*64;
    float v0 = xr[lane], v1 = xr[lane+32];
    float s = v0 + v1;
    #pragma unroll
    for (int o = 16; o; o >>= 1) s += __shfl_xor_sync(0xffffffffu, s, o);
    float mean = s * (1.0f/64.0f);
    float d0 = v0 - mean, d1 = v1 - mean;
    float s2 = d0*d0 + d1*d1;
    #pragma unroll
    for (int o = 16; o; o >>= 1) s2 += __shfl_xor_sync(0xffffffffu, s2, o);
    float inv = rsqrtf(s2 * (1.0f/64.0f) + 1e-5f);
    float xn0 = fmaf(d0 * inv, lg[lane],    lb[lane]);
    float xn1 = fmaf(d1 * inv, lg[lane+32], lb[lane+32]);
    float lgt[5];
    #pragma unroll
    for (int c = 0; c < 5; c++) {
        float t = fmaf(xn0, pw[lane*5 + c], xn1 * pw[(lane+32)*5 + c]);
        #pragma unroll
        for (int o = 16; o; o >>= 1) t += __shfl_xor_sync(0xffffffffu, t, o);
        lgt[c] = t + pb[c];
    }
    float m = lgt[0];
    #pragma unroll
    for (int c = 1; c < 5; c++) m = fmaxf(m, lgt[c]);
    float e[5], se = 0.f;
    #pragma unroll
    for (int c = 0; c < 5; c++) { e[c] = __expf(lgt[c] - m); se += e[c]; }
    float rse = 1.0f / se;
    if (lane == 0) {
        #pragma unroll
        for (int c = 0; c < 5; c++) outp[row*5 + c] = e[c] * rse;
    }
}

extern "C" void kernel_launch(void* const* d_in, const int* in_sizes, int n_in,
                              void* d_out, int out_size)
{
    const float* x_enc   = (const float*)d_in[0];
    const int*   idxs    = (const int*)  d_in[1];
    const float* emb_w   = (const float*)d_in[2];
    const float* Wq      = (const float*)d_in[3];
    const float* bq      = (const float*)d_in[4];
    const float* Wk      = (const float*)d_in[5];
    const float* bk      = (const float*)d_in[6];
    const float* Wv      = (const float*)d_in[7];
    const float* bv      = (const float*)d_in[8];
    const float* Wo      = (const float*)d_in[9];
    const float* bo      = (const float*)d_in[10];
    const float* c1w     = (const float*)d_in[11];
    const float* c1b     = (const float*)d_in[12];
    const float* c2w     = (const float*)d_in[13];
    const float* c2b     = (const float*)d_in[14];
    const float* ln1g    = (const float*)d_in[15];
    const float* ln1b    = (const float*)d_in[16];
    const float* ln2g    = (const float*)d_in[17];
    const float* ln2b    = (const float*)d_in[18];
    const float* lnfg    = (const float*)d_in[19];
    const float* lnfb    = (const float*)d_in[20];
    const float* projw   = (const float*)d_in[21];
    const float* projb   = (const float*)d_in[22];
    float* outp = (float*)d_out;

    cudaStream_t s1;
    cudaStreamCreateWithFlags(&s1, cudaStreamNonBlocking);
    cudaEvent_t evF[2], evJ[2];
    for (int i = 0; i < 2; i++) {
        cudaEventCreateWithFlags(&evF[i], cudaEventDisableTiming);
        cudaEventCreateWithFlags(&evJ[i], cudaEventDisableTiming);
    }

    k_div<<<1, 32>>>();
    k_embed<<<ROWS*DM/256, 256>>>(x_enc, emb_w);

    for (int i = 0; i < 2; i++) {
        k_qkv<<<dim3(ROWS/32, 3), 256>>>(Wq + i*DM*DM, bq + i*DM, Wk + i*DM*DM, bk + i*DM,
                                         Wv + i*DM*DM, bv + i*DM);
        cudaEventRecord(evF[i], 0);
        cudaStreamWaitEvent(s1, evF[i], 0);
        k_vpart<<<BB*VSEG, 256, 0, s1>>>();
        k_vmean<<<1, BB*DM, 0, s1>>>();
        k_vmc<<<ROWS*DM/256, 256, 0, s1>>>();
        cudaEventRecord(evJ[i], s1);
        k_mscore<<<ROWS/8, 256>>>(idxs + i*LL*UU);
        k_topk<<<BB*HH, 256>>>();
        k_attn<<<BB*HH*NSPLIT, 256>>>();
        cudaStreamWaitEvent(0, evJ[i], 0);
        k_merge<<<BB*HH*UU*8/256, 256>>>();
        k_wo_ln<<<ROWS/32, 256>>>(Wo + i*DM*DM, bo + i*DM, ln1g + i*DM, ln1b + i*DM);
        k_ffn<<<ROWS/32, 256>>>(c1w + i*DM*DFF, c1b + i*DFF, c2w + i*DFF*DM, c2b + i*DM,
                                ln2g + i*DM, ln2b + i*DM);
    }
    k_final<<<ROWS/8, 256>>>(lnfg, lnfb, projw, projb, outp);
}

// round 15
// speedup vs baseline: 1.1173x; 1.0484x over previous
#include <cuda_runtime.h>
#include <cuda_bf16.h>
#include <math.h>
#include <stdint.h>

#define BB 4
#define LL 8192
#define DM 64
#define HH 8
#define DFF 256
#define UU 50
#define ROWS (BB*LL)
#define CHUNK 512
#define NSPLIT 16
#define VSEG 64

typedef unsigned long long u64;

__device__ __align__(16) float g_x[ROWS*DM];
__device__ __align__(16) float g_q[ROWS*DM];
__device__ __align__(16) float g_k[ROWS*DM];
__device__ __align__(16) float g_v[ROWS*DM];
__device__ __align__(16) __nv_bfloat16 g_kh[ROWS*DM];
__device__ __align__(16) float g_ctx[ROWS*DM];
__device__ float g_M[BB*HH*LL];
__device__ int   g_top[BB*HH*UU];
__device__ float g_vpart[BB*VSEG*DM];
__device__ float g_vmean[BB*DM];
__device__ float g_part[BB*HH*UU*NSPLIT*10];

// ---- packed fp32x2 helpers (bit-exact: each half is an IEEE fp32 FMA) ----
__device__ __forceinline__ u64 pk2(float lo, float hi) {
    u64 r;
    asm("mov.b64 %0, {%1, %2};" : "=l"(r) : "r"(__float_as_uint(lo)), "r"(__float_as_uint(hi)));
    return r;
}
__device__ __forceinline__ void upk2(u64 v, float &lo, float &hi) {
    unsigned a, b;
    asm("mov.b64 {%0, %1}, %2;" : "=r"(a), "=r"(b) : "l"(v));
    lo = __uint_as_float(a); hi = __uint_as_float(b);
}
__device__ __forceinline__ void fma2(u64 &d, u64 a, u64 b) {
    asm("fma.rn.f32x2 %0, %1, %2, %0;" : "+l"(d) : "l"(a), "l"(b));
}

__device__ __forceinline__ unsigned fkey(float f) {
    unsigned u = __float_as_uint(f);
    return (u & 0x80000000u) ? ~u : (u | 0x80000000u);
}

// embed with the fp64 div table computed per-block in smem (identical bits to the
// old k_div kernel; removes one serial launch from the critical path)
__global__ void k_embed(const float* __restrict__ xe, const float* __restrict__ ew) {
    __shared__ float2 sdiv[32];
    if (threadIdx.x < 32) {
        int i = threadIdx.x;
        double dvd = exp(((double)(-2*i)) * (log(10000.0) / 64.0));
        float hi = (float)dvd;
        sdiv[i] = make_float2(hi, (float)(dvd - (double)hi));
    }
    __syncthreads();
    int gid = blockIdx.x*256 + threadIdx.x;
    int d = gid & 63, row = gid >> 6;
    int l = row & (LL-1), b = row >> 13;
    const float* xb = xe + b*LL;
    float tok = ew[d*3+0]*xb[(l+LL-1)&(LL-1)] + ew[d*3+1]*xb[l] + ew[d*3+2]*xb[(l+1)&(LL-1)];
    float2 dv = sdiv[d >> 1];
    float lf = (float)l;
    float ph = lf * dv.x;
    float perr = fmaf(lf, dv.x, -ph);
    float plo = fmaf(lf, dv.y, perr);
    float kq = rintf(ph * 0.63661977236758134f);
    float r = fmaf(-kq, 1.57079637050628662109375f, ph);
    r = fmaf(kq, 4.37113900018624283e-08f, r);
    r += plo;
    int qd = (((int)kq) + (d & 1)) & 3;
    float sr = sinf(r), cr = cosf(r);
    float pe = (qd == 0) ? sr : (qd == 1) ? cr : (qd == 2) ? -sr : -cr;
    g_x[gid] = tok + pe;
}

__global__ __launch_bounds__(256) void k_qkv(
    const float* __restrict__ Wq, const float* __restrict__ bq,
    const float* __restrict__ Wk, const float* __restrict__ bk,
    const float* __restrict__ Wv, const float* __restrict__ bv)
{
    __shared__ __align__(16) float xT[64*36];
    int row0 = blockIdx.x * 32, tid = threadIdx.x;
    for (int i = tid; i < 2048; i += 256) { int c=i&63, r=i>>6; xT[c*36+r] = g_x[(row0+r)*64+c]; }
    __syncthreads();
    int col = tid & 63, rg = tid >> 6;
    u64 aq2[4], ak2[4], av2[4];
    #pragma unroll
    for (int p = 0; p < 4; p++) { aq2[p]=0ull; ak2[p]=0ull; av2[p]=0ull; }
    #pragma unroll 4
    for (int kk = 0; kk < 64; kk++) {
        u64 wq2 = pk2(Wq[kk*64+col], Wq[kk*64+col]);
        u64 wk2 = pk2(Wk[kk*64+col], Wk[kk*64+col]);
        u64 wv2 = pk2(Wv[kk*64+col], Wv[kk*64+col]);
        const u64* xp = reinterpret_cast<const u64*>(&xT[kk*36 + rg*8]);
        #pragma unroll
        for (int p = 0; p < 4; p++) {
            u64 xv = xp[p];
            fma2(aq2[p], xv, wq2);
            fma2(ak2[p], xv, wk2);
            fma2(av2[p], xv, wv2);
        }
    }
    float b1 = bq[col], b2 = bk[col], b3 = bv[col];
    #pragma unroll
    for (int p = 0; p < 4; p++) {
        float q0,q1,k0,k1,v0,v1;
        upk2(aq2[p], q0, q1); upk2(ak2[p], k0, k1); upk2(av2[p], v0, v1);
        int row = row0 + rg*8 + 2*p;
        float kv0 = k0 + b2, kv1 = k1 + b2;
        g_q[row*64+col] = q0 + b1;       g_q[(row+1)*64+col] = q1 + b1;
        g_k[row*64+col] = kv0;           g_k[(row+1)*64+col] = kv1;
        g_kh[row*64+col] = __float2bfloat16(kv0);
        g_kh[(row+1)*64+col] = __float2bfloat16(kv1);
        g_v[row*64+col] = v0 + b3;       g_v[(row+1)*64+col] = v1 + b3;
    }
}

// M-score via bf16 shadow-k: 32 lanes = 4 rows x 8 heads; 16B load = one head row-slice
__global__ __launch_bounds__(256) void k_mscore(const int* __restrict__ idxs)
{
    int wid = blockIdx.x*8 + (threadIdx.x>>5);
    int lane = threadIdx.x & 31;
    int b = wid >> 13, l = wid & (LL-1);
    const int* ib = idxs + l*UU;
    int i1 = ib[lane];
    int i2 = (lane < 18) ? ib[32+lane] : 0;
    int h = lane & 7;
    int rgrp = lane >> 3;
    const float4* qp = reinterpret_cast<const float4*>(g_q + (b*LL + l)*64 + h*8);
    float4 qa = qp[0], qb_ = qp[1];
    float runmax = -INFINITY, runsum = 0.f;
    #pragma unroll
    for (int it = 0; it < 13; it++) {
        int r = it*4 + rgrp;
        int idx = (r < 32) ? __shfl_sync(0xffffffffu, i1, r)
                           : __shfl_sync(0xffffffffu, i2, r-32);
        if (r < UU) {
            uint4 raw = reinterpret_cast<const uint4*>(g_kh + (b*LL + idx)*64)[h];
            float2 f0 = __bfloat1622float2(*reinterpret_cast<__nv_bfloat162*>(&raw.x));
            float2 f1 = __bfloat1622float2(*reinterpret_cast<__nv_bfloat162*>(&raw.y));
            float2 f2 = __bfloat1622float2(*reinterpret_cast<__nv_bfloat162*>(&raw.z));
            float2 f3 = __bfloat1622float2(*reinterpret_cast<__nv_bfloat162*>(&raw.w));
            float dd = qa.x*f0.x;
            dd = fmaf(qa.y, f0.y, dd);
            dd = fmaf(qa.z, f1.x, dd);
            dd = fmaf(qa.w, f1.y, dd);
            dd = fmaf(qb_.x, f2.x, dd);
            dd = fmaf(qb_.y, f2.y, dd);
            dd = fmaf(qb_.z, f3.x, dd);
            dd = fmaf(qb_.w, f3.y, dd);
            runmax = fmaxf(runmax, dd);
            runsum += dd;
        }
    }
    runmax = fmaxf(runmax, __shfl_xor_sync(0xffffffffu, runmax, 8));
    runsum +=              __shfl_xor_sync(0xffffffffu, runsum, 8);
    runmax = fmaxf(runmax, __shfl_xor_sync(0xffffffffu, runmax, 16));
    runsum +=              __shfl_xor_sync(0xffffffffu, runsum, 16);
    if (lane < 8)
        g_M[(b*HH + h)*LL + l] = runmax - runsum * (1.0f/8192.0f);
}

// Exact top-50 as a SET via 4-pass MSB radix select (order irrelevant; ties at
// threshold filled by smallest index — set-equivalent to jax.lax.top_k)
__global__ __launch_bounds__(256) void k_topk()
{
    __shared__ unsigned sK[8192];
    __shared__ int hist[256];
    __shared__ unsigned sPrefix;
    __shared__ int sRem;
    __shared__ int cnt, eqcnt;
    __shared__ int eqbuf[256];
    int bh = blockIdx.x, tid = threadIdx.x;
    const float* base = g_M + bh*LL;
    for (int i = tid; i < 8192; i += 256) sK[i] = fkey(base[i]);
    if (tid == 0) { sPrefix = 0; sRem = UU; cnt = 0; eqcnt = 0; }
    __syncthreads();
    unsigned prefmask = 0;
    #pragma unroll
    for (int pass = 0; pass < 4; pass++) {
        int shift = 24 - 8*pass;
        hist[tid] = 0;
        __syncthreads();
        unsigned pref = sPrefix;
        for (int i = tid; i < 8192; i += 256) {
            unsigned u = sK[i];
            if ((u & prefmask) == pref)
                atomicAdd(&hist[(u >> shift) & 0xffu], 1);
        }
        __syncthreads();
        if (tid == 0) {
            int acc = 0, rem = sRem;
            for (int bkt = 255; bkt >= 0; bkt--) {
                int hh = hist[bkt];
                if (acc + hh >= rem) { sPrefix = pref | ((unsigned)bkt << shift); sRem = rem - acc; break; }
                acc += hh;
            }
        }
        __syncthreads();
        prefmask |= 0xffu << shift;
    }
    unsigned T = sPrefix;
    int need = sRem;
    for (int i = tid; i < 8192; i += 256) {
        unsigned u = sK[i];
        if (u > T) {
            int p = atomicAdd(&cnt, 1);
            g_top[bh*UU + p] = i;
        } else if (u == T) {
            int p = atomicAdd(&eqcnt, 1);
            if (p < 256) eqbuf[p] = i;
        }
    }
    __syncthreads();
    if (tid == 0) {
        int basep = cnt;
        int ec = eqcnt < 256 ? eqcnt : 256;
        for (int r = 0; r < need; r++) {
            int best = 0x7fffffff, bj = 0;
            for (int j = 0; j < ec; j++)
                if (eqbuf[j] < best) { best = eqbuf[j]; bj = j; }
            eqbuf[bj] = 0x7fffffff;
            g_top[bh*UU + basep + r] = best;
        }
    }
}

__global__ void k_vpart()
{
    __shared__ float sm[4][64];
    int b = blockIdx.x >> 6, seg = blockIdx.x & 63;
    int d = threadIdx.x & 63, lg = threadIdx.x >> 6;
    const float* base = g_v + (b*LL + seg*128 + lg*32)*64 + d;
    float s = 0.f;
    #pragma unroll 8
    for (int i = 0; i < 32; i++) s += base[i*64];
    sm[lg][d] = s;
    __syncthreads();
    if (threadIdx.x < 64)
        g_vpart[(b*VSEG + seg)*64 + threadIdx.x] =
            sm[0][threadIdx.x] + sm[1][threadIdx.x] + sm[2][threadIdx.x] + sm[3][threadIdx.x];
}

__global__ void k_vmean()
{
    int t = threadIdx.x;
    int b = t >> 6, d = t & 63;
    float s = 0.f;
    #pragma unroll
    for (int i = 0; i < VSEG; i++) s += g_vpart[(b*VSEG+i)*64 + d];
    g_vmean[t] = s * (1.0f/8192.0f);
}

__global__ void k_vmc()
{
    int gid = blockIdx.x*256 + threadIdx.x;
    g_ctx[gid] = g_vmean[((gid >> 19) << 6) | (gid & 63)];
}

template<int G>
__device__ __forceinline__ void attn_group(
    int u0, int bh, int b, int h, int lane, int split,
    const float* kT, const float* vT)
{
    const float SCALE = 0.35355339059327373f;
    float4 qa[G], qb[G];
    int uu[G]; bool val[G];
    #pragma unroll
    for (int g = 0; g < G; g++) {
        int u = u0 + g*8;
        val[g] = (u < UU);
        uu[g] = val[g] ? u : 0;
        int qi = g_top[bh*UU + uu[g]];
        const float4* qp = reinterpret_cast<const float4*>(g_q + (b*LL + qi)*64 + h*8);
        qa[g] = qp[0]; qb[g] = qp[1];
    }
    float ssum[G];
    u64 pv2[G][4];
    #pragma unroll
    for (int g = 0; g < G; g++) {
        ssum[g] = 0.f;
        #pragma unroll
        for (int e = 0; e < 4; e++) pv2[g][e] = 0ull;
    }
    for (int j = lane; j < CHUNK; j += 32) {
        float k0 = kT[j],        k1 = kT[520+j],   k2 = kT[2*520+j], k3 = kT[3*520+j];
        float k4 = kT[4*520+j],  k5 = kT[5*520+j], k6 = kT[6*520+j], k7 = kT[7*520+j];
        u64 v01 = pk2(vT[j],        vT[520+j]);
        u64 v23 = pk2(vT[2*520+j],  vT[3*520+j]);
        u64 v45 = pk2(vT[4*520+j],  vT[5*520+j]);
        u64 v67 = pk2(vT[6*520+j],  vT[7*520+j]);
        #pragma unroll
        for (int g = 0; g < G; g++) {
            float s = qa[g].x*k0;
            s = fmaf(qa[g].y, k1, s);
            s = fmaf(qa[g].z, k2, s);
            s = fmaf(qa[g].w, k3, s);
            s = fmaf(qb[g].x, k4, s);
            s = fmaf(qb[g].y, k5, s);
            s = fmaf(qb[g].z, k6, s);
            s = fmaf(qb[g].w, k7, s);
            float p = __expf(s * SCALE);
            ssum[g] += p;
            u64 p2 = pk2(p, p);
            fma2(pv2[g][0], v01, p2);
            fma2(pv2[g][1], v23, p2);
            fma2(pv2[g][2], v45, p2);
            fma2(pv2[g][3], v67, p2);
        }
    }
    #pragma unroll
    for (int g = 0; g < G; g++) {
        float pv[8];
        #pragma unroll
        for (int e = 0; e < 4; e++) upk2(pv2[g][e], pv[2*e], pv[2*e+1]);
        #pragma unroll
        for (int o = 16; o; o >>= 1) {
            ssum[g] += __shfl_xor_sync(0xffffffffu, ssum[g], o);
            #pragma unroll
            for (int e = 0; e < 8; e++) pv[e] += __shfl_xor_sync(0xffffffffu, pv[e], o);
        }
        if (lane == 0 && val[g]) {
            float* pp = g_part + ((bh*UU + uu[g])*NSPLIT + split)*10;
            #pragma unroll
            for (int e = 0; e < 8; e++) pp[e] = pv[e];
            pp[8] = ssum[g];
        }
    }
}

__global__ __launch_bounds__(256) void k_attn()
{
    __shared__ float kT[8*520];
    __shared__ float vT[8*520];
    int bh = blockIdx.x >> 4, split = blockIdx.x & 15;
    int b = bh >> 3, h = bh & 7;
    int l0 = split * CHUNK, tid = threadIdx.x;
    for (int i = tid; i < CHUNK*8; i += 256) {
        int j = i >> 3, e = i & 7;
        int g = (b*LL + l0 + j)*64 + h*8 + e;
        kT[e*520 + j] = g_k[g];
        vT[e*520 + j] = g_v[g];
    }
    __syncthreads();
    int w = tid >> 5, lane = tid & 31;
    attn_group<4>(w,      bh, b, h, lane, split, kT, vT);
    attn_group<3>(w + 32, bh, b, h, lane, split, kT, vT);
}

__global__ void k_merge()
{
    int gid = blockIdx.x*256 + threadIdx.x;
    int e = gid & 7, rest = gid >> 3;
    int u = rest % UU, bh = rest / UU;
    int b = bh >> 3, h = bh & 7;
    const float* pp = g_part + ((bh*UU + u)*NSPLIT)*10;
    float pv = 0.f, ss = 0.f;
    for (int s = 0; s < NSPLIT; s++) { pv += pp[s*10 + e]; ss += pp[s*10 + 8]; }
    int qi = g_top[bh*UU + u];
    g_ctx[(b*LL + qi)*64 + h*8 + e] = pv / ss;
}

__device__ __forceinline__ void ln_epilogue(float* out65, int row0, int tid,
    const float* __restrict__ lg, const float* __restrict__ lb)
{
    int w = tid >> 5, lane = tid & 31;
    float gg0 = lg[lane], gg1 = lg[lane+32], bb0 = lb[lane], bb1 = lb[lane+32];
    #pragma unroll
    for (int rr = 0; rr < 4; rr++) {
        int r = w*4 + rr;
        float v0 = out65[r*65 + lane], v1 = out65[r*65 + lane + 32];
        float s = v0 + v1;
        #pragma unroll
        for (int o = 16; o; o >>= 1) s += __shfl_xor_sync(0xffffffffu, s, o);
        float mean = s * (1.0f/64.0f);
        float d0 = v0 - mean, d1 = v1 - mean;
        float s2 = d0*d0 + d1*d1;
        #pragma unroll
        for (int o = 16; o; o >>= 1) s2 += __shfl_xor_sync(0xffffffffu, s2, o);
        float inv = rsqrtf(s2 * (1.0f/64.0f) + 1e-5f);
        int go = (row0 + r)*64;
        g_x[go + lane]      = fmaf(d0 * inv, gg0, bb0);
        g_x[go + lane + 32] = fmaf(d1 * inv, gg1, bb1);
    }
}

__global__ __launch_bounds__(256) void k_wo_ln(
    const float* __restrict__ W, const float* __restrict__ bo,
    const float* __restrict__ lg, const float* __restrict__ lb)
{
    __shared__ __align__(16) float xT[64*36];
    __shared__ float out[32*65];
    int row0 = blockIdx.x * 32, tid = threadIdx.x;
    for (int i = tid; i < 2048; i += 256) { int c=i&63, r=i>>6; xT[c*36+r] = g_ctx[(row0+r)*64+c]; }
    __syncthreads();
    int col = tid & 63, rg = tid >> 6;
    u64 acc2[4];
    #pragma unroll
    for (int p = 0; p < 4; p++) acc2[p] = 0ull;
    #pragma unroll 4
    for (int kk = 0; kk < 64; kk++) {
        float wvv = W[kk*64+col];
        u64 w2 = pk2(wvv, wvv);
        const u64* xp = reinterpret_cast<const u64*>(&xT[kk*36 + rg*8]);
        #pragma unroll
        for (int p = 0; p < 4; p++) fma2(acc2[p], xp[p], w2);
    }
    float bv2 = bo[col];
    #pragma unroll
    for (int p = 0; p < 4; p++) {
        float f0, f1;
        upk2(acc2[p], f0, f1);
        int r = rg*8 + 2*p;
        out[r*65 + col]     = f0 + bv2 + g_x[(row0 + r)*64 + col];
        out[(r+1)*65 + col] = f1 + bv2 + g_x[(row0 + r + 1)*64 + col];
    }
    __syncthreads();
    ln_epilogue(out, row0, tid, lg, lb);
}

__global__ __launch_bounds__(256) void k_ffn(
    const float* __restrict__ W1, const float* __restrict__ b1,
    const float* __restrict__ W2, const float* __restrict__ b2,
    const float* __restrict__ lg, const float* __restrict__ lb)
{
    __shared__ __align__(16) float yT[256*36];
    __shared__ __align__(16) float xTo[64*36];
    int row0 = blockIdx.x * 32, tid = threadIdx.x;
    for (int i = tid; i < 2048; i += 256) { int c=i&63, r=i>>6; xTo[c*36+r] = g_x[(row0+r)*64+c]; }
    __syncthreads();
    int col = tid & 63, rg = tid >> 6;
    u64 acc2[16];
    #pragma unroll
    for (int i = 0; i < 16; i++) acc2[i] = 0ull;
    #pragma unroll 2
    for (int kk = 0; kk < 64; kk++) {
        u64 w0 = pk2(W1[kk*256 + col],       W1[kk*256 + col]);
        u64 w1 = pk2(W1[kk*256 + 64 + col],  W1[kk*256 + 64 + col]);
        u64 w2 = pk2(W1[kk*256 + 128 + col], W1[kk*256 + 128 + col]);
        u64 w3 = pk2(W1[kk*256 + 192 + col], W1[kk*256 + 192 + col]);
        const u64* xp = reinterpret_cast<const u64*>(&xTo[kk*36 + rg*8]);
        #pragma unroll
        for (int p = 0; p < 4; p++) {
            u64 xv = xp[p];
            fma2(acc2[p],    xv, w0);
            fma2(acc2[4+p],  xv, w1);
            fma2(acc2[8+p],  xv, w2);
            fma2(acc2[12+p], xv, w3);
        }
    }
    __syncthreads();
    #pragma unroll
    for (int t = 0; t < 4; t++) {
        float bb = b1[t*64 + col];
        float f[8];
        #pragma unroll
        for (int p = 0; p < 4; p++) {
            float a, c;
            upk2(acc2[t*4+p], a, c);
            f[2*p]   = fmaxf(a + bb, 0.f);
            f[2*p+1] = fmaxf(c + bb, 0.f);
        }
        float4 f0 = {f[0], f[1], f[2], f[3]};
        float4 f1 = {f[4], f[5], f[6], f[7]};
        *reinterpret_cast<float4*>(&yT[(t*64+col)*36 + rg*8])     = f0;
        *reinterpret_cast<float4*>(&yT[(t*64+col)*36 + rg*8 + 4]) = f1;
    }
    __syncthreads();
    u64 a2[4];
    #pragma unroll
    for (int p = 0; p < 4; p++) a2[p] = 0ull;
    #pragma unroll 4
    for (int kk = 0; kk < 256; kk++) {
        float wvv = W2[kk*64 + col];
        u64 w2 = pk2(wvv, wvv);
        const u64* yp = reinterpret_cast<const u64*>(&yT[kk*36 + rg*8]);
        #pragma unroll
        for (int p = 0; p < 4; p++) fma2(a2[p], yp[p], w2);
    }
    float bv2 = b2[col];
    float* out = xTo;
    #pragma unroll
    for (int p = 0; p < 4; p++) {
        float f0, f1;
        upk2(a2[p], f0, f1);
        int r = rg*8 + 2*p;
        out[r*65 + col]     = f0 + bv2 + g_x[(row0 + r)*64 + col];
        out[(r+1)*65 + col] = f1 + bv2 + g_x[(row0 + r + 1)*64 + col];
    }
    __syncthreads();
    ln_epilogue(out, row0, tid, lg, lb);
}

__global__ __launch_bounds__(256) void k_final(
    const float* __restrict__ lg, const float* __restrict__ lb,
    const float* __restrict__ pw, const float* __restrict__ pb,
    float* __restrict__ outp)
{
    int row = blockIdx.x*8 + (threadIdx.x >> 5);
    int lane = threadIdx.x & 31;
    const float* xr = g_x + row*64;
    float v0 = xr[lane], v1 = xr[lane+32];
    float s = v0 + v1;
    #pragma unroll
    for (int o = 16; o; o >>= 1) s += __shfl_xor_sync(0xffffffffu, s, o);
    float mean = s * (1.0f/64.0f);
    float d0 = v0 - mean, d1 = v1 - mean;
    float s2 = d0*d0 + d1*d1;
    #pragma unroll
    for (int o = 16; o; o >>= 1) s2 += __shfl_xor_sync(0xffffffffu, s2, o);
    float inv = rsqrtf(s2 * (1.0f/64.0f) + 1e-5f);
    float xn0 = fmaf(d0 * inv, lg[lane],    lb[lane]);
    float xn1 = fmaf(d1 * inv, lg[lane+32], lb[lane+32]);
    float lgt[5];
    #pragma unroll
    for (int c = 0; c < 5; c++) {
        float t = fmaf(xn0, pw[lane*5 + c], xn1 * pw[(lane+32)*5 + c]);
        #pragma unroll
        for (int o = 16; o; o >>= 1) t += __shfl_xor_sync(0xffffffffu, t, o);
        lgt[c] = t + pb[c];
    }
    float m = lgt[0];
    #pragma unroll
    for (int c = 1; c < 5; c++) m = fmaxf(m, lgt[c]);
    float e[5], se = 0.f;
    #pragma unroll
    for (int c = 0; c < 5; c++) { e[c] = __expf(lgt[c] - m); se += e[c]; }
    float rse = 1.0f / se;
    if (lane == 0) {
        #pragma unroll
        for (int c = 0; c < 5; c++) outp[row*5 + c] = e[c] * rse;
    }
}

extern "C" void kernel_launch(void* const* d_in, const int* in_sizes, int n_in,
                              void* d_out, int out_size)
{
    const float* x_enc   = (const float*)d_in[0];
    const int*   idxs    = (const int*)  d_in[1];
    const float* emb_w   = (const float*)d_in[2];
    const float* Wq      = (const float*)d_in[3];
    const float* bq      = (const float*)d_in[4];
    const float* Wk      = (const float*)d_in[5];
    const float* bk      = (const float*)d_in[6];
    const float* Wv      = (const float*)d_in[7];
    const float* bv      = (const float*)d_in[8];
    const float* Wo      = (const float*)d_in[9];
    const float* bo      = (const float*)d_in[10];
    const float* c1w     = (const float*)d_in[11];
    const float* c1b     = (const float*)d_in[12];
    const float* c2w     = (const float*)d_in[13];
    const float* c2b     = (const float*)d_in[14];
    const float* ln1g    = (const float*)d_in[15];
    const float* ln1b    = (const float*)d_in[16];
    const float* ln2g    = (const float*)d_in[17];
    const float* ln2b    = (const float*)d_in[18];
    const float* lnfg    = (const float*)d_in[19];
    const float* lnfb    = (const float*)d_in[20];
    const float* projw   = (const float*)d_in[21];
    const float* projb   = (const float*)d_in[22];
    float* outp = (float*)d_out;

    cudaStream_t s1;
    cudaStreamCreateWithFlags(&s1, cudaStreamNonBlocking);
    cudaEvent_t evF[2], evJ[2];
    for (int i = 0; i < 2; i++) {
        cudaEventCreateWithFlags(&evF[i], cudaEventDisableTiming);
        cudaEventCreateWithFlags(&evJ[i], cudaEventDisableTiming);
    }

    k_embed<<<ROWS*DM/256, 256>>>(x_enc, emb_w);

    for (int i = 0; i < 2; i++) {
        k_qkv<<<ROWS/32, 256>>>(Wq + i*DM*DM, bq + i*DM, Wk + i*DM*DM, bk + i*DM,
                                Wv + i*DM*DM, bv + i*DM);
        cudaEventRecord(evF[i], 0);
        cudaStreamWaitEvent(s1, evF[i], 0);
        k_vpart<<<BB*VSEG, 256, 0, s1>>>();
        k_vmean<<<1, BB*DM, 0, s1>>>();
        k_vmc<<<ROWS*DM/256, 256, 0, s1>>>();
        cudaEventRecord(evJ[i], s1);
        k_mscore<<<ROWS/8, 256>>>(idxs + i*LL*UU);
        k_topk<<<BB*HH, 256>>>();
        k_attn<<<BB*HH*NSPLIT, 256>>>();
        cudaStreamWaitEvent(0, evJ[i], 0);
        k_merge<<<BB*HH*UU*8/256, 256>>>();
        k_wo_ln<<<ROWS/32, 256>>>(Wo + i*DM*DM, bo + i*DM, ln1g + i*DM, ln1b + i*DM);
        k_ffn<<<ROWS/32, 256>>>(c1w + i*DM*DFF, c1b + i*DFF, c2w + i*DFF*DM, c2b + i*DM,
                                ln2g + i*DM, ln2b + i*DM);
    }
    k_final<<<ROWS/8, 256>>>(lnfg, lnfb, projw, projb, outp);
}